// round 10
// baseline (speedup 1.0000x reference)
#include <cuda_runtime.h>
#include <cstdint>

#define BB 16
#define NN 2048
#define MM 1024
#define TT 256

#define SCALE_C (4.5392368437151541e-04f)  // 1/sqrt(1920^2+1080^2)
#define A_TRK 2.0f
#define A_SPA 1.5f
#define A_TMP 1.8f
#define B_FP 0.9f
#define B_FN 0.9f
#define G_SW 1.5f

#define NCX 8
#define NCELL 64
#define CELL_SCALE 0.008f       // 1/125
#define F_INF __int_as_float(0x7f800000)

#define K3_PB 64                 // blocks per batch (32 preds each)
#define K3_TOTAL (K3_PB * BB)    // 1024

// ---------------- device scratch (no allocations allowed) ----------------
__device__ int    g_gt_cnt[BB][TT];
__device__ int    g_pr_cnt[BB][TT];
__device__ int    g_csr_off[BB][TT];    // exclusive prefix of gt_cnt (track CSR)
__device__ int    g_csr[BB][MM];        // SORTED gt positions grouped by track id
__device__ float4 g_sgb[BB][MM];        // cell-sorted gt boxes
__device__ float  g_sa2[BB][MM];        // cell-sorted a2 (or +INF if track has no preds)
__device__ int    g_goff[BB][NCELL + 1];// gt cell CSR offsets
__device__ int    g_pord[BB][NN];       // cell-sorted pred original indices
__device__ float  g_fn[BB];
__device__ int    g_nuni[BB];
__device__ int    g_nvalid[BB];
__device__ float  g_match[BB];
__device__ float  g_fp[BB];
__device__ int    g_sw[BB];
__device__ float  g_spatial[BB];
__device__ float  g_traw[BB];           // finalized in K1 now
__device__ int    g_done;

// ======================= K1: hists + spatial + temporal + 4 CSR builds =======================
__global__ __launch_bounds__(1024) void k1_prep(
    const float4* __restrict__ pboxes,
    const float4* __restrict__ gboxes,
    const int*    __restrict__ pid,
    const int*    __restrict__ gid)
{
    const int b = blockIdx.x;
    const int tid = threadIdx.x;
    const int lane = tid & 31, w = tid >> 5;

    __shared__ int   s_gt[TT], s_pr[TT];
    __shared__ float s_mw[TT], s_mh[TT], s_dw[TT], s_dh[TT];
    __shared__ int   s_toff[TT], s_tcur[TT];
    __shared__ int   s_proff[TT], s_prcur[TT];
    __shared__ float s_w[NN], s_h[NN];     // s_w re-used as pred-track index list later
    __shared__ int   s_p[NN];              // packed: pid | (cell<<8)
    __shared__ float s_ga2[MM];
    __shared__ int   s_gcid[MM];
    __shared__ int   s_gcnt[NCELL], s_goffs[NCELL], s_gcur[NCELL];
    __shared__ int   s_pcnt[NCELL], s_poffs[NCELL], s_pcur[NCELL];
    __shared__ int   s_wsum[8], s_wsum2[8];
    __shared__ int   s_ct[4];
    __shared__ float r_f[32], r_s[32], r_t[32];
    __shared__ int   r_u[32], r_v[32];

    if (tid < TT) {
        s_gt[tid] = 0; s_pr[tid] = 0;
        s_mw[tid] = 0.f; s_mh[tid] = 0.f;
        s_dw[tid] = 0.f; s_dh[tid] = 0.f;
    }
    if (tid < NCELL) {
        s_gcnt[tid] = 0; s_gcur[tid] = 0;
        s_pcnt[tid] = 0; s_pcur[tid] = 0;
    }
    if (b == 0 && tid == 0) g_done = 0;
    if (tid == 0) { g_match[b] = 0.f; g_fp[b] = 0.f; g_sw[b] = 0; }
    __syncthreads();

    // ---- phase 1: histograms + stashes ----
    const int* gidb = gid + b * MM;
    const float4* gb4 = gboxes + b * MM;
    if (tid < MM) {
        float4 g = gb4[tid];
        int t = gidb[tid];
        float a2 = fmaxf(g.z - g.x, 0.f) * fmaxf(g.w - g.y, 0.f);
        int cx = min((int)(g.x * CELL_SCALE), 7);
        int cy = min((int)(g.y * CELL_SCALE), 7);
        int c = cy * NCX + cx;
        s_ga2[tid] = a2;
        s_gcid[tid] = c;
        atomicAdd(&s_gt[t], 1);
        atomicAdd(&s_gcnt[c], 1);
    }
    const int* pidb = pid + b * NN;
    const float4* pb4 = pboxes + b * NN;
    int nvalid = 0;
    #pragma unroll
    for (int k = 0; k < 2; k++) {
        int i = tid + k * 1024;
        int p = pidb[i];
        float4 bx = pb4[i];
        float bw = bx.z - bx.x, bh = bx.w - bx.y;
        int cx = min((int)(bx.x * CELL_SCALE), 7);
        int cy = min((int)(bx.y * CELL_SCALE), 7);
        int c = cy * NCX + cx;
        s_w[i] = bw; s_h[i] = bh;
        s_p[i] = p | (c << 8);             // pid in [0,255]
        atomicAdd(&s_pcnt[c], 1);
        if (p > 0) {
            atomicAdd(&s_pr[p], 1);
            atomicAdd(&s_mw[p], bw);
            atomicAdd(&s_mh[p], bh);
            nvalid++;
        }
    }
    __syncthreads();

    // ---- phase 2: 4 prefix scans ----
    int c_gt = 0, vinc = 0;
    int cellv = 0, cellincl = 0;
    int prv = 0, princl = 0;
    if (tid < TT) {
        int c = s_pr[tid];
        float cs = fmaxf((float)c, 1.f);
        s_mw[tid] = s_mw[tid] / cs;
        s_mh[tid] = s_mh[tid] / cs;
        g_pr_cnt[b][tid] = c;
        c_gt = s_gt[tid];
        g_gt_cnt[b][tid] = c_gt;
        vinc = c_gt;
        #pragma unroll
        for (int o = 1; o < 32; o <<= 1) {
            int n = __shfl_up_sync(0xffffffffu, vinc, o);
            if (lane >= o) vinc += n;
        }
        if (lane == 31) s_wsum[w] = vinc;
    } else if (tid < 320) {          // gt cell scan
        int c = tid - 256;
        cellv = s_gcnt[c];
        cellincl = cellv;
        #pragma unroll
        for (int o = 1; o < 32; o <<= 1) {
            int n = __shfl_up_sync(0xffffffffu, cellincl, o);
            if (lane >= o) cellincl += n;
        }
        if (lane == 31) s_ct[w - 8] = cellincl;   // idx 0,1
    } else if (tid < 384) {          // pred cell scan
        int c = tid - 320;
        cellv = s_pcnt[c];
        cellincl = cellv;
        #pragma unroll
        for (int o = 1; o < 32; o <<= 1) {
            int n = __shfl_up_sync(0xffffffffu, cellincl, o);
            if (lane >= o) cellincl += n;
        }
        if (lane == 31) s_ct[w - 8] = cellincl;   // idx 2,3
    } else if (tid < 640) {          // pred-track scan (warps 12-19)
        int c = tid - 384;
        prv = s_pr[c];
        princl = prv;
        #pragma unroll
        for (int o = 1; o < 32; o <<= 1) {
            int n = __shfl_up_sync(0xffffffffu, princl, o);
            if (lane >= o) princl += n;
        }
        if (lane == 31) s_wsum2[w - 12] = princl;
    }
    __syncthreads();
    if (tid < TT) {
        int woff = 0;
        #pragma unroll
        for (int k = 0; k < 8; k++) if (k < w) woff += s_wsum[k];
        int excl = woff + vinc - c_gt;
        s_toff[tid] = excl;
        s_tcur[tid] = 0;
        g_csr_off[b][tid] = excl;
    } else if (tid < 320) {
        int c = tid - 256;
        int excl = cellincl - cellv + ((c >= 32) ? s_ct[0] : 0);
        s_goffs[c] = excl;
        g_goff[b][c] = excl;
        if (c == 0) g_goff[b][NCELL] = MM;
    } else if (tid < 384) {
        int c = tid - 320;
        int excl = cellincl - cellv + ((c >= 32) ? s_ct[2] : 0);
        s_poffs[c] = excl;
    } else if (tid < 640) {
        int c = tid - 384;
        int woff = 0;
        int ww = w - 12;
        #pragma unroll
        for (int k = 0; k < 8; k++) if (k < ww) woff += s_wsum2[k];
        s_proff[c] = woff + princl - prv;
        s_prcur[c] = 0;
    }
    __syncthreads();

    // ---- phase 3a: deviations + pord + gt scatter ----
    #pragma unroll
    for (int k = 0; k < 2; k++) {
        int i = tid + k * 1024;
        int pk = s_p[i];
        int p = pk & 0xFF;
        int c = pk >> 8;
        if (p > 0) {
            atomicAdd(&s_dw[p], fabsf(s_w[i] - s_mw[p]));
            atomicAdd(&s_dh[p], fabsf(s_h[i] - s_mh[p]));
        }
        int pos = s_poffs[c] + atomicAdd(&s_pcur[c], 1);
        g_pord[b][pos] = i;
    }
    if (tid < MM) {
        int j = tid;
        float4 g = gb4[j];
        int t = gidb[j];
        int c = s_gcid[j];
        int pos = s_goffs[c] + atomicAdd(&s_gcur[c], 1);
        g_sgb[b][pos] = g;
        g_sa2[b][pos] = (s_pr[t] > 0) ? s_ga2[j] : F_INF;
        int tp = s_toff[t] + atomicAdd(&s_tcur[t], 1);
        g_csr[b][tp] = pos;                          // sorted position
    }
    __syncthreads();

    // ---- phase 3b: pred-track list scatter (aliases s_w; s_w/s_h dead now) ----
    int* tpl = (int*)s_w;
    #pragma unroll
    for (int k = 0; k < 2; k++) {
        int i = tid + k * 1024;
        int p = s_p[i] & 0xFF;
        if (p > 0) {
            int pos = s_proff[p] + atomicAdd(&s_prcur[p], 1);
            tpl[pos] = i;
        }
    }
    __syncthreads();

    // ---- phase 3c + 4: per-track sort + temporal + terms + block reduce ----
    float fn = 0.f, sp = 0.f, tp = 0.f;
    int nu = 0;
    if (tid < TT) {
        int c  = s_pr[tid];
        int gc = s_gt[tid];
        fn = (gc > 0 && c == 0) ? (float)gc : 0.f;
        nu = (c > 0) ? 1 : 0;
        sp = (c > 1) ? (s_dw[tid] + s_dh[tid]) * SCALE_C / (float)c : 0.f;
        if (tid > 0 && c > 2) {
            const int off = s_proff[tid];
            // insertion sort indices ascending (restores original order)
            for (int a = off + 1; a < off + c; a++) {
                int key = tpl[a];
                int q = a - 1;
                while (q >= off && tpl[q] > key) { tpl[q + 1] = tpl[q]; q--; }
                tpl[q + 1] = key;
            }
            float c0x = 0.f, c0y = 0.f, c1x = 0.f, c1y = 0.f;
            float sa = 0.f;
            for (int k = 0; k < c; k++) {
                int j = tpl[off + k];
                float4 bxx = pb4[j];               // L1-resident
                float cx = (bxx.x + bxx.z) * 0.5f;
                float cy = (bxx.y + bxx.w) * 0.5f;
                if (k >= 2) {
                    float ax = (cx - 2.f * c1x + c0x) * SCALE_C;
                    float ay = (cy - 2.f * c1y + c0y) * SCALE_C;
                    sa += sqrtf(ax * ax + ay * ay);
                }
                c0x = c1x; c0y = c1y; c1x = cx; c1y = cy;
            }
            tp = sa / (float)(c - 2);
        }
    }
    #pragma unroll
    for (int o = 16; o > 0; o >>= 1) {
        fn     += __shfl_down_sync(0xffffffffu, fn, o);
        sp     += __shfl_down_sync(0xffffffffu, sp, o);
        tp     += __shfl_down_sync(0xffffffffu, tp, o);
        nu     += __shfl_down_sync(0xffffffffu, nu, o);
        nvalid += __shfl_down_sync(0xffffffffu, nvalid, o);
    }
    if (lane == 0) { r_f[w] = fn; r_s[w] = sp; r_t[w] = tp; r_u[w] = nu; r_v[w] = nvalid; }
    __syncthreads();
    if (tid == 0) {
        float F = 0.f, S = 0.f, T = 0.f; int U = 0, V = 0;
        #pragma unroll
        for (int k = 0; k < 32; k++) { F += r_f[k]; S += r_s[k]; T += r_t[k]; U += r_u[k]; V += r_v[k]; }
        g_fn[b] = F; g_nuni[b] = U; g_nvalid[b] = V;
        g_spatial[b] = (V > 1) ? S / fmaxf((float)U, 1.f) : 0.f;
        g_traw[b] = T;
    }
}

// ======================= K3: windowed IoU (SMEM) + match + finalize =======================
// grid (64, BB), 256 threads. 32 preds/block; 8 warps stride the window j-loop.
__global__ __launch_bounds__(256) void k3_main(
    const float4* __restrict__ pboxes,
    const int*    __restrict__ pid,
    float* __restrict__ out)
{
    const int b = blockIdx.y;
    const int bx = blockIdx.x;
    const int tid = threadIdx.x;
    const int lane = tid & 31;
    const int wid = tid >> 5;

    __shared__ __align__(16) float4 s_gb[MM];   // sorted gt boxes  16 KB
    __shared__ __align__(16) float  s_a2[MM];   // sorted a2/INF     4 KB
    __shared__ int s_goff[NCELL + 1];
    __shared__ int s_last;

    const float4* __restrict__ sgbg = g_sgb[b];
    const float*  __restrict__ sa2g = g_sa2[b];
    #pragma unroll
    for (int k = 0; k < 4; k++) {
        int j = tid + k * 256;
        s_gb[j] = sgbg[j];
        s_a2[j] = sa2g[j];
    }
    if (tid < NCELL + 1) s_goff[tid] = g_goff[b][tid];
    __syncthreads();

    const int pred_l = tid & 31;
    const int msplit = wid;                      // warp-uniform 8-way split
    const int slot = bx * 32 + pred_l;
    const int idx = g_pord[b][slot];
    const int p = __ldg(&pid[b * NN + idx]);
    const float4 pbx = __ldg(&pboxes[b * NN + idx]);
    const float px1 = pbx.x, py1 = pbx.y, px2 = pbx.z, py2 = pbx.w;
    const float a1r = fmaxf(px2 - px1, 0.f) * fmaxf(py2 - py1, 0.f);
    const float a1 = (p > 0) ? a1r : F_INF;      // INF => hi-test always false

    // window cells (conservative: gt corner in [px1-102, px2] x [py1-102, py2])
    int cx0 = (int)(fmaxf(px1 - 103.f, 0.f) * CELL_SCALE);
    int cx1 = min((int)((px2 + 1.f) * CELL_SCALE), 7);
    int cy0 = (int)(fmaxf(py1 - 103.f, 0.f) * CELL_SCALE);
    int cy1 = min((int)((py2 + 1.f) * CELL_SCALE), 7);
    #pragma unroll
    for (int o = 16; o > 0; o >>= 1) {
        cx0 = min(cx0, __shfl_xor_sync(0xffffffffu, cx0, o));
        cx1 = max(cx1, __shfl_xor_sync(0xffffffffu, cx1, o));
        cy0 = min(cy0, __shfl_xor_sync(0xffffffffu, cy0, o));
        cy1 = max(cy1, __shfl_xor_sync(0xffffffffu, cy1, o));
    }
    // all 8 warps hold the SAME 32 preds -> identical window; strided j covers each pair once

    int swc = 0;
    for (int cy = cy0; cy <= cy1; cy++) {
        const int rowb = cy * NCX;
        const int jlo = s_goff[rowb + cx0];
        const int jhi = s_goff[rowb + cx1 + 1];
        #pragma unroll 2
        for (int j = jlo + msplit; j < jhi; j += 8) {     // warp-uniform broadcast
            float4 g = s_gb[j];
            float a2 = s_a2[j];
            float lx = fmaxf(px1, g.x), ly = fmaxf(py1, g.y);
            float rx = fminf(px2, g.z), ry = fminf(py2, g.w);
            float inter = (rx - lx) * fmaxf(ry - ly, 0.f);   // single-clamp
            swc += (fmaf(3.f, inter, -a1) > a2);
        }
    }

    float matchv = 0.f, fpv = 0.f;
    if (msplit == 0 && p > 0) {
        int gc = g_gt_cnt[b][p];
        if (gc > 0) {
            int off = g_csr_off[b][p];
            float bn = 0.f, bd = 1.f;
            for (int k = 0; k < gc; k++) {
                int pos = g_csr[b][off + k];
                float4 g = s_gb[pos];
                float a2 = s_a2[pos];            // own track => finite
                float lx = fmaxf(px1, g.x), ly = fmaxf(py1, g.y);
                float rx = fminf(px2, g.z), ry = fminf(py2, g.w);
                float iw = rx - lx;
                float ihc = fmaxf(ry - ly, 0.f);
                float interh = iw * ihc;                       // identical hi-test
                swc -= (fmaf(3.f, interh, -a1) > a2);
                float inter = fmaxf(iw, 0.f) * ihc;            // true inter for IoU
                float uni = a1r + a2 - inter;
                if (inter * bd > bn * uni) { bn = inter; bd = uni; }
            }
            matchv = 1.f - __fdividef(bn, bd);
        } else {
            fpv = 1.f;
        }
    }

    #pragma unroll
    for (int o = 16; o > 0; o >>= 1) {
        matchv += __shfl_down_sync(0xffffffffu, matchv, o);
        fpv    += __shfl_down_sync(0xffffffffu, fpv, o);
        swc    += __shfl_down_sync(0xffffffffu, swc, o);
    }
    if (lane == 0) {
        atomicAdd(&g_match[b], matchv);
        atomicAdd(&g_fp[b], fpv);
        atomicAdd(&g_sw[b], swc);
    }

    // ---- last-block-done finalize ----
    __syncthreads();
    if (tid == 0) {
        __threadfence();
        int prev = atomicAdd(&g_done, 1);
        s_last = (prev == K3_TOTAL - 1) ? 1 : 0;
    }
    __syncthreads();
    if (s_last && tid < 32) {
        __threadfence();
        float lt = 0.f, ls = 0.f, lm = 0.f, nt = 0.f;
        if (tid < BB) {
            int bb = tid;
            int nv = g_nvalid[bb];
            int nu = g_nuni[bb];
            float has = (nv > 0) ? 1.f : 0.f;
            float mt  = *((volatile float*)&g_match[bb]);
            float fpb = *((volatile float*)&g_fp[bb]);
            int   sw  = *((volatile int*)&g_sw[bb]);
            float trw = g_traw[bb];
            float tr = B_FN * g_fn[bb] + mt + G_SW * (float)sw + B_FP * fpb;
            float tmp = (nv > 2) ? trw / fmaxf((float)nu, 1.f) : 0.f;
            lt = tr * has;
            ls = g_spatial[bb] * has;
            lm = tmp * has;
            nt = (float)nu * has;
        }
        #pragma unroll
        for (int o = 16; o > 0; o >>= 1) {
            lt += __shfl_down_sync(0xffffffffu, lt, o);
            ls += __shfl_down_sync(0xffffffffu, ls, o);
            lm += __shfl_down_sync(0xffffffffu, lm, o);
            nt += __shfl_down_sync(0xffffffffu, nt, o);
        }
        if (tid == 0) {
            float norm = (nt > 0.f) ? nt : 1.f;
            lt /= norm; ls /= norm; lm /= norm;
            out[0] = A_TRK * lt + A_SPA * ls + A_TMP * lm;
            out[1] = lt;
            out[2] = ls;
            out[3] = lm;
        }
    }
}

// ======================= launch =======================
extern "C" void kernel_launch(void* const* d_in, const int* in_sizes, int n_in,
                              void* d_out, int out_size)
{
    const float4* pb  = (const float4*)d_in[0];  // pred_boxes [16,2048,4] f32
    const float4* gb  = (const float4*)d_in[1];  // gt_boxes   [16,1024,4] f32
    const int*    pid = (const int*)d_in[2];     // pred_track_ids [16,2048] i32
    const int*    gid = (const int*)d_in[3];     // gt_track_ids   [16,1024] i32
    float* out = (float*)d_out;

    k1_prep<<<BB, 1024>>>(pb, gb, pid, gid);
    k3_main<<<dim3(K3_PB, BB), 256>>>(pb, pid, out);
}

// round 11
// speedup vs baseline: 1.0416x; 1.0416x over previous
#include <cuda_runtime.h>
#include <cstdint>

#define BB 16
#define NN 2048
#define MM 1024
#define TT 256

#define SCALE_C (4.5392368437151541e-04f)  // 1/sqrt(1920^2+1080^2)
#define A_TRK 2.0f
#define A_SPA 1.5f
#define A_TMP 1.8f
#define B_FP 0.9f
#define B_FN 0.9f
#define G_SW 1.5f

#define NCX 8
#define NCELL 64
#define CELL_SCALE 0.008f       // 1/125
#define F_INF __int_as_float(0x7f800000)

#define K3_PB 32                 // blocks per batch (64 preds each)
#define K3_TOTAL (K3_PB * BB)    // 512

// ---------------- device scratch (no allocations allowed) ----------------
__device__ int    g_gt_cnt[BB][TT];
__device__ int    g_pr_cnt[BB][TT];
__device__ int    g_csr_off[BB][TT];    // exclusive prefix of gt_cnt (track CSR)
__device__ int    g_csr[BB][MM];        // SORTED gt positions grouped by track id
__device__ float4 g_sgb[BB][MM];        // cell-sorted gt boxes
__device__ float  g_sa2[BB][MM];        // cell-sorted a2 (or +INF if track has no preds)
__device__ int    g_goff[BB][NCELL + 1];// gt cell CSR offsets
__device__ int    g_pord[BB][NN];       // cell-sorted pred original indices
__device__ float  g_fn[BB];
__device__ int    g_nuni[BB];
__device__ int    g_nvalid[BB];
__device__ float  g_match[BB];
__device__ float  g_fp[BB];
__device__ int    g_sw[BB];
__device__ float  g_spatial[BB];
__device__ float  g_traw[BB];
__device__ int    g_done;

// ======================= K1: hists + spatial + 3 CSR builds =======================
__global__ __launch_bounds__(1024) void k1_prep(
    const float4* __restrict__ pboxes,
    const float4* __restrict__ gboxes,
    const int*    __restrict__ pid,
    const int*    __restrict__ gid)
{
    const int b = blockIdx.x;
    const int tid = threadIdx.x;
    const int lane = tid & 31, w = tid >> 5;

    __shared__ int   s_gt[TT], s_pr[TT];
    __shared__ float s_mw[TT], s_mh[TT], s_dw[TT], s_dh[TT];
    __shared__ int   s_toff[TT], s_tcur[TT];
    __shared__ float s_w[NN], s_h[NN];
    __shared__ int   s_p[NN];              // packed: pid | (cell<<8)
    __shared__ float s_ga2[MM];
    __shared__ int   s_gcid[MM];
    __shared__ int   s_gcnt[NCELL], s_goffs[NCELL], s_gcur[NCELL];
    __shared__ int   s_pcnt[NCELL], s_poffs[NCELL], s_pcur[NCELL];
    __shared__ int   s_wsum[8];
    __shared__ int   s_ct[4];
    __shared__ float r_f[32], r_s[32];
    __shared__ int   r_u[32], r_v[32];

    if (tid < TT) {
        s_gt[tid] = 0; s_pr[tid] = 0;
        s_mw[tid] = 0.f; s_mh[tid] = 0.f;
        s_dw[tid] = 0.f; s_dh[tid] = 0.f;
    }
    if (tid < NCELL) {
        s_gcnt[tid] = 0; s_gcur[tid] = 0;
        s_pcnt[tid] = 0; s_pcur[tid] = 0;
    }
    if (b == 0 && tid == 0) g_done = 0;
    if (tid == 0) { g_match[b] = 0.f; g_fp[b] = 0.f; g_sw[b] = 0; g_traw[b] = 0.f; }
    __syncthreads();

    // ---- phase 1: histograms + stashes ----
    const int* gidb = gid + b * MM;
    const float4* gb4 = gboxes + b * MM;
    if (tid < MM) {
        float4 g = gb4[tid];
        int t = gidb[tid];
        float a2 = fmaxf(g.z - g.x, 0.f) * fmaxf(g.w - g.y, 0.f);
        int cx = min((int)(g.x * CELL_SCALE), 7);
        int cy = min((int)(g.y * CELL_SCALE), 7);
        int c = cy * NCX + cx;
        s_ga2[tid] = a2;
        s_gcid[tid] = c;
        atomicAdd(&s_gt[t], 1);
        atomicAdd(&s_gcnt[c], 1);
    }
    const int* pidb = pid + b * NN;
    const float4* pb4 = pboxes + b * NN;
    int nvalid = 0;
    #pragma unroll
    for (int k = 0; k < 2; k++) {
        int i = tid + k * 1024;
        int p = pidb[i];
        float4 bx = pb4[i];
        float bw = bx.z - bx.x, bh = bx.w - bx.y;
        int cx = min((int)(bx.x * CELL_SCALE), 7);
        int cy = min((int)(bx.y * CELL_SCALE), 7);
        int c = cy * NCX + cx;
        s_w[i] = bw; s_h[i] = bh;
        s_p[i] = p | (c << 8);             // pid in [0,255]
        atomicAdd(&s_pcnt[c], 1);
        if (p > 0) {
            atomicAdd(&s_pr[p], 1);
            atomicAdd(&s_mw[p], bw);
            atomicAdd(&s_mh[p], bh);
            nvalid++;
        }
    }
    __syncthreads();

    // ---- phase 2: prefix scans (track: warps 0-7; gt cells: warps 8-9; pred cells: warps 10-11) ----
    int c_gt = 0, vinc = 0;
    int cellv = 0, cellincl = 0;
    if (tid < TT) {
        int c = s_pr[tid];
        float cs = fmaxf((float)c, 1.f);
        s_mw[tid] = s_mw[tid] / cs;
        s_mh[tid] = s_mh[tid] / cs;
        g_pr_cnt[b][tid] = c;
        c_gt = s_gt[tid];
        g_gt_cnt[b][tid] = c_gt;
        vinc = c_gt;
        #pragma unroll
        for (int o = 1; o < 32; o <<= 1) {
            int n = __shfl_up_sync(0xffffffffu, vinc, o);
            if (lane >= o) vinc += n;
        }
        if (lane == 31) s_wsum[w] = vinc;
    } else if (tid < 320) {          // gt cell scan
        int c = tid - 256;
        cellv = s_gcnt[c];
        cellincl = cellv;
        #pragma unroll
        for (int o = 1; o < 32; o <<= 1) {
            int n = __shfl_up_sync(0xffffffffu, cellincl, o);
            if (lane >= o) cellincl += n;
        }
        if (lane == 31) s_ct[w - 8] = cellincl;   // idx 0,1
    } else if (tid < 384) {          // pred cell scan
        int c = tid - 320;
        cellv = s_pcnt[c];
        cellincl = cellv;
        #pragma unroll
        for (int o = 1; o < 32; o <<= 1) {
            int n = __shfl_up_sync(0xffffffffu, cellincl, o);
            if (lane >= o) cellincl += n;
        }
        if (lane == 31) s_ct[w - 8] = cellincl;   // idx 2,3
    }
    __syncthreads();
    if (tid < TT) {
        int woff = 0;
        #pragma unroll
        for (int k = 0; k < 8; k++) if (k < w) woff += s_wsum[k];
        int excl = woff + vinc - c_gt;
        s_toff[tid] = excl;
        s_tcur[tid] = 0;
        g_csr_off[b][tid] = excl;
    } else if (tid < 320) {
        int c = tid - 256;
        int excl = cellincl - cellv + ((c >= 32) ? s_ct[0] : 0);
        s_goffs[c] = excl;
        g_goff[b][c] = excl;
        if (c == 0) g_goff[b][NCELL] = MM;
    } else if (tid < 384) {
        int c = tid - 320;
        int excl = cellincl - cellv + ((c >= 32) ? s_ct[2] : 0);
        s_poffs[c] = excl;
    }
    __syncthreads();

    // ---- phase 3: deviations + all scatters ----
    #pragma unroll
    for (int k = 0; k < 2; k++) {
        int i = tid + k * 1024;
        int pk = s_p[i];
        int p = pk & 0xFF;
        int c = pk >> 8;
        if (p > 0) {
            atomicAdd(&s_dw[p], fabsf(s_w[i] - s_mw[p]));
            atomicAdd(&s_dh[p], fabsf(s_h[i] - s_mh[p]));
        }
        int pos = s_poffs[c] + atomicAdd(&s_pcur[c], 1);
        g_pord[b][pos] = i;
    }
    if (tid < MM) {
        int j = tid;
        float4 g = gb4[j];
        int t = gidb[j];
        int c = s_gcid[j];
        int pos = s_goffs[c] + atomicAdd(&s_gcur[c], 1);
        g_sgb[b][pos] = g;
        g_sa2[b][pos] = (s_pr[t] > 0) ? s_ga2[j] : F_INF;
        int tp = s_toff[t] + atomicAdd(&s_tcur[t], 1);
        g_csr[b][tp] = pos;                          // sorted position
    }
    __syncthreads();

    // ---- phase 4: per-track terms + block reduce ----
    float fn = 0.f, sp = 0.f;
    int nu = 0;
    if (tid < TT) {
        int c  = s_pr[tid];
        int gc = s_gt[tid];
        fn = (gc > 0 && c == 0) ? (float)gc : 0.f;
        nu = (c > 0) ? 1 : 0;
        sp = (c > 1) ? (s_dw[tid] + s_dh[tid]) * SCALE_C / (float)c : 0.f;
    }
    #pragma unroll
    for (int o = 16; o > 0; o >>= 1) {
        fn     += __shfl_down_sync(0xffffffffu, fn, o);
        sp     += __shfl_down_sync(0xffffffffu, sp, o);
        nu     += __shfl_down_sync(0xffffffffu, nu, o);
        nvalid += __shfl_down_sync(0xffffffffu, nvalid, o);
    }
    if (lane == 0) { r_f[w] = fn; r_s[w] = sp; r_u[w] = nu; r_v[w] = nvalid; }
    __syncthreads();
    if (tid == 0) {
        float F = 0.f, S = 0.f; int U = 0, V = 0;
        #pragma unroll
        for (int k = 0; k < 32; k++) { F += r_f[k]; S += r_s[k]; U += r_u[k]; V += r_v[k]; }
        g_fn[b] = F; g_nuni[b] = U; g_nvalid[b] = V;
        g_spatial[b] = (V > 1) ? S / fmaxf((float)U, 1.f) : 0.f;
    }
}

// ======================= K3: windowed IoU (__ldg, no gt staging) + match + temporal + finalize ==
// grid (32, BB), 256 threads. 64 preds/block; 4 warp-groups stride the window j-loop.
__global__ __launch_bounds__(256) void k3_main(
    const float4* __restrict__ pboxes,
    const int*    __restrict__ pid,
    float* __restrict__ out)
{
    const int b = blockIdx.y;
    const int bx = blockIdx.x;
    const int tid = threadIdx.x;
    const int lane = tid & 31;
    const int wid = tid >> 5;

    __shared__ int s_p[NN];                     // pred ids   8 KB
    __shared__ int s_goff[NCELL + 1];
    __shared__ int s_last;

    const int* pidb = pid + b * NN;
    #pragma unroll
    for (int k = 0; k < 8; k++) {
        int i = tid + k * 256;
        s_p[i] = pidb[i];
    }
    if (tid < NCELL + 1) s_goff[tid] = g_goff[b][tid];
    __syncthreads();

    const float4* __restrict__ sgb = g_sgb[b];
    const float*  __restrict__ sa2 = g_sa2[b];

    const int pred_l = tid & 63;
    const int msplit = tid >> 6;                 // warp-uniform (wid>>1)
    const int slot = bx * 64 + pred_l;
    const int idx = g_pord[b][slot];
    const int p = s_p[idx];
    const float4 pbx = __ldg(&pboxes[b * NN + idx]);
    const float px1 = pbx.x, py1 = pbx.y, px2 = pbx.z, py2 = pbx.w;
    const float a1r = fmaxf(px2 - px1, 0.f) * fmaxf(py2 - py1, 0.f);
    const float a1 = (p > 0) ? a1r : F_INF;      // INF => hi-test always false

    // window cells (conservative: gt corner in [px1-102, px2] x [py1-102, py2])
    int cx0 = (int)(fmaxf(px1 - 103.f, 0.f) * CELL_SCALE);
    int cx1 = min((int)((px2 + 1.f) * CELL_SCALE), 7);
    int cy0 = (int)(fmaxf(py1 - 103.f, 0.f) * CELL_SCALE);
    int cy1 = min((int)((py2 + 1.f) * CELL_SCALE), 7);
    #pragma unroll
    for (int o = 16; o > 0; o >>= 1) {
        cx0 = min(cx0, __shfl_xor_sync(0xffffffffu, cx0, o));
        cx1 = max(cx1, __shfl_xor_sync(0xffffffffu, cx1, o));
        cy0 = min(cy0, __shfl_xor_sync(0xffffffffu, cy0, o));
        cy1 = max(cy1, __shfl_xor_sync(0xffffffffu, cy1, o));
    }

    int swc = 0;
    for (int cy = cy0; cy <= cy1; cy++) {
        const int rowb = cy * NCX;
        const int jlo = s_goff[rowb + cx0];
        const int jhi = s_goff[rowb + cx1 + 1];
        #pragma unroll 4
        for (int j = jlo + msplit; j < jhi; j += 4) {     // warp-uniform broadcast loads
            float4 g = __ldg(&sgb[j]);
            float a2 = __ldg(&sa2[j]);
            float lx = fmaxf(px1, g.x), ly = fmaxf(py1, g.y);
            float rx = fminf(px2, g.z), ry = fminf(py2, g.w);
            float inter = (rx - lx) * fmaxf(ry - ly, 0.f);   // single-clamp
            swc += (fmaf(3.f, inter, -a1) > a2);
        }
    }

    float matchv = 0.f, fpv = 0.f;
    if (msplit == 0 && p > 0) {
        int gc = g_gt_cnt[b][p];
        if (gc > 0) {
            int off = g_csr_off[b][p];
            float bn = 0.f, bd = 1.f;
            for (int k = 0; k < gc; k++) {
                int pos = g_csr[b][off + k];
                float4 g = __ldg(&sgb[pos]);
                float a2 = __ldg(&sa2[pos]);     // own track => finite
                float lx = fmaxf(px1, g.x), ly = fmaxf(py1, g.y);
                float rx = fminf(px2, g.z), ry = fminf(py2, g.w);
                float iw = rx - lx;
                float ihc = fmaxf(ry - ly, 0.f);
                float interh = iw * ihc;                       // identical hi-test
                swc -= (fmaf(3.f, interh, -a1) > a2);
                float inter = fmaxf(iw, 0.f) * ihc;            // true inter for IoU
                float uni = a1r + a2 - inter;
                if (inter * bd > bn * uni) { bn = inter; bd = uni; }
            }
            matchv = 1.f - __fdividef(bn, bd);
        } else {
            fpv = 1.f;
        }
    }

    #pragma unroll
    for (int o = 16; o > 0; o >>= 1) {
        matchv += __shfl_down_sync(0xffffffffu, matchv, o);
        fpv    += __shfl_down_sync(0xffffffffu, fpv, o);
        swc    += __shfl_down_sync(0xffffffffu, swc, o);
    }
    if (lane == 0) {
        atomicAdd(&g_match[b], matchv);
        atomicAdd(&g_fp[b], fpv);
        atomicAdd(&g_sw[b], swc);
    }

    // ---- temporal: ONE track per warp, ballot scan over SMEM in original order ----
    {
        const int t = bx * 8 + wid;              // 0..255, warp-uniform
        const float4* pb4 = pboxes + b * NN;
        const int cnt = (t > 0) ? g_pr_cnt[b][t] : 0;
        if (cnt > 2) {
            float c0x = 0.f, c0y = 0.f, c1x = 0.f, c1y = 0.f;
            int seen = 0;
            float sa = 0.f;
            for (int base = 0; base < NN; base += 32) {
                int pp = s_p[base + lane];
                unsigned m = __ballot_sync(0xffffffffu, pp == t);
                while (m) {
                    int j = base + (__ffs(m) - 1);
                    m &= m - 1;
                    float4 bxx = __ldg(&pb4[j]);     // rare hit: L1/L2
                    float cx = (bxx.x + bxx.z) * 0.5f;
                    float cy = (bxx.y + bxx.w) * 0.5f;
                    if (seen >= 2) {
                        float ax = (cx - 2.f * c1x + c0x) * SCALE_C;
                        float ay = (cy - 2.f * c1y + c0y) * SCALE_C;
                        sa += sqrtf(ax * ax + ay * ay);
                    }
                    c0x = c1x; c0y = c1y; c1x = cx; c1y = cy;
                    seen++;
                }
            }
            if (lane == 0)
                atomicAdd(&g_traw[b], sa / (float)(cnt - 2));
        }
    }

    // ---- last-block-done finalize ----
    __syncthreads();
    if (tid == 0) {
        __threadfence();
        int prev = atomicAdd(&g_done, 1);
        s_last = (prev == K3_TOTAL - 1) ? 1 : 0;
    }
    __syncthreads();
    if (s_last && tid < 32) {
        __threadfence();
        float lt = 0.f, ls = 0.f, lm = 0.f, nt = 0.f;
        if (tid < BB) {
            int bb = tid;
            int nv = g_nvalid[bb];
            int nu = g_nuni[bb];
            float has = (nv > 0) ? 1.f : 0.f;
            float mt  = *((volatile float*)&g_match[bb]);
            float fpb = *((volatile float*)&g_fp[bb]);
            int   sw  = *((volatile int*)&g_sw[bb]);
            float trw = *((volatile float*)&g_traw[bb]);
            float tr = B_FN * g_fn[bb] + mt + G_SW * (float)sw + B_FP * fpb;
            float tmp = (nv > 2) ? trw / fmaxf((float)nu, 1.f) : 0.f;
            lt = tr * has;
            ls = g_spatial[bb] * has;
            lm = tmp * has;
            nt = (float)nu * has;
        }
        #pragma unroll
        for (int o = 16; o > 0; o >>= 1) {
            lt += __shfl_down_sync(0xffffffffu, lt, o);
            ls += __shfl_down_sync(0xffffffffu, ls, o);
            lm += __shfl_down_sync(0xffffffffu, lm, o);
            nt += __shfl_down_sync(0xffffffffu, nt, o);
        }
        if (tid == 0) {
            float norm = (nt > 0.f) ? nt : 1.f;
            lt /= norm; ls /= norm; lm /= norm;
            out[0] = A_TRK * lt + A_SPA * ls + A_TMP * lm;
            out[1] = lt;
            out[2] = ls;
            out[3] = lm;
        }
    }
}

// ======================= launch =======================
extern "C" void kernel_launch(void* const* d_in, const int* in_sizes, int n_in,
                              void* d_out, int out_size)
{
    const float4* pb  = (const float4*)d_in[0];  // pred_boxes [16,2048,4] f32
    const float4* gb  = (const float4*)d_in[1];  // gt_boxes   [16,1024,4] f32
    const int*    pid = (const int*)d_in[2];     // pred_track_ids [16,2048] i32
    const int*    gid = (const int*)d_in[3];     // gt_track_ids   [16,1024] i32
    float* out = (float*)d_out;

    k1_prep<<<BB, 1024>>>(pb, gb, pid, gid);
    k3_main<<<dim3(K3_PB, BB), 256>>>(pb, pid, out);
}

// round 12
// speedup vs baseline: 1.1598x; 1.1134x over previous
#include <cuda_runtime.h>
#include <cstdint>

#define BB 16
#define NN 2048
#define MM 1024
#define TT 256

#define SCALE_C (4.5392368437151541e-04f)  // 1/sqrt(1920^2+1080^2)
#define A_TRK 2.0f
#define A_SPA 1.5f
#define A_TMP 1.8f
#define B_FP 0.9f
#define B_FN 0.9f
#define G_SW 1.5f

#define NCX 8
#define NCELL 64
#define CELL_SCALE 0.008f       // 1/125
#define F_INF __int_as_float(0x7f800000)

#define K3_PB 32                 // blocks per batch (64 preds each)
#define K3_TOTAL (K3_PB * BB)    // 512

// ---------------- device scratch (no allocations allowed) ----------------
__device__ int    g_gt_cnt[BB][TT];
__device__ int    g_pr_cnt[BB][TT];
__device__ int    g_csr_off[BB][TT];    // exclusive prefix of gt_cnt (track CSR)
__device__ int    g_csr[BB][MM];        // SORTED gt positions grouped by track id
__device__ float4 g_sgb[BB][MM];        // cell-sorted gt boxes
__device__ float  g_sa2[BB][MM];        // cell-sorted a2 (or +INF if track has no preds)
__device__ int    g_goff[BB][NCELL + 1];// gt cell CSR offsets
__device__ int    g_pord[BB][NN];       // cell-sorted pred original indices
__device__ float  g_fn[BB];
__device__ int    g_nuni[BB];
__device__ int    g_nvalid[BB];
__device__ float  g_match[BB];
__device__ float  g_fp[BB];
__device__ int    g_sw[BB];
__device__ float  g_spatial[BB];
__device__ float  g_traw[BB];           // finalized in K1 (warp-parallel temporal)
__device__ int    g_done;

// ======================= K1: hists + spatial + temporal + CSR builds =======================
__global__ __launch_bounds__(1024) void k1_prep(
    const float4* __restrict__ pboxes,
    const float4* __restrict__ gboxes,
    const int*    __restrict__ pid,
    const int*    __restrict__ gid)
{
    const int b = blockIdx.x;
    const int tid = threadIdx.x;
    const int lane = tid & 31, w = tid >> 5;

    __shared__ int   s_gt[TT], s_pr[TT];
    __shared__ float s_mw[TT], s_mh[TT], s_dw[TT], s_dh[TT];
    __shared__ int   s_toff[TT], s_tcur[TT];
    __shared__ int   s_proff[TT], s_prcur[TT];
    __shared__ float s_w[NN], s_h[NN];     // s_w aliased as track-pred list later
    __shared__ int   s_p[NN];              // packed: pid | (cell<<8)
    __shared__ float s_ga2[MM];
    __shared__ int   s_gcid[MM];
    __shared__ int   s_gcnt[NCELL], s_goffs[NCELL], s_gcur[NCELL];
    __shared__ int   s_pcnt[NCELL], s_poffs[NCELL], s_pcur[NCELL];
    __shared__ int   s_wsum[8], s_wsum2[8];
    __shared__ int   s_ct[4];
    __shared__ float r_f[32], r_s[32], r_t[32];
    __shared__ int   r_u[32], r_v[32];

    if (tid < TT) {
        s_gt[tid] = 0; s_pr[tid] = 0;
        s_mw[tid] = 0.f; s_mh[tid] = 0.f;
        s_dw[tid] = 0.f; s_dh[tid] = 0.f;
    }
    if (tid < NCELL) {
        s_gcnt[tid] = 0; s_gcur[tid] = 0;
        s_pcnt[tid] = 0; s_pcur[tid] = 0;
    }
    if (b == 0 && tid == 0) g_done = 0;
    if (tid == 0) { g_match[b] = 0.f; g_fp[b] = 0.f; g_sw[b] = 0; }
    __syncthreads();

    // ---- phase 1: histograms + stashes ----
    const int* gidb = gid + b * MM;
    const float4* gb4 = gboxes + b * MM;
    if (tid < MM) {
        float4 g = gb4[tid];
        int t = gidb[tid];
        float a2 = fmaxf(g.z - g.x, 0.f) * fmaxf(g.w - g.y, 0.f);
        int cx = min((int)(g.x * CELL_SCALE), 7);
        int cy = min((int)(g.y * CELL_SCALE), 7);
        int c = cy * NCX + cx;
        s_ga2[tid] = a2;
        s_gcid[tid] = c;
        atomicAdd(&s_gt[t], 1);
        atomicAdd(&s_gcnt[c], 1);
    }
    const int* pidb = pid + b * NN;
    const float4* pb4 = pboxes + b * NN;
    int nvalid = 0;
    #pragma unroll
    for (int k = 0; k < 2; k++) {
        int i = tid + k * 1024;
        int p = pidb[i];
        float4 bx = pb4[i];
        float bw = bx.z - bx.x, bh = bx.w - bx.y;
        int cx = min((int)(bx.x * CELL_SCALE), 7);
        int cy = min((int)(bx.y * CELL_SCALE), 7);
        int c = cy * NCX + cx;
        s_w[i] = bw; s_h[i] = bh;
        s_p[i] = p | (c << 8);             // pid in [0,255]
        atomicAdd(&s_pcnt[c], 1);
        if (p > 0) {
            atomicAdd(&s_pr[p], 1);
            atomicAdd(&s_mw[p], bw);
            atomicAdd(&s_mh[p], bh);
            nvalid++;
        }
    }
    __syncthreads();

    // ---- phase 2: 4 prefix scans ----
    int c_gt = 0, vinc = 0;
    int cellv = 0, cellincl = 0;
    int prv = 0, princl = 0;
    if (tid < TT) {
        int c = s_pr[tid];
        float cs = fmaxf((float)c, 1.f);
        s_mw[tid] = s_mw[tid] / cs;
        s_mh[tid] = s_mh[tid] / cs;
        g_pr_cnt[b][tid] = c;
        c_gt = s_gt[tid];
        g_gt_cnt[b][tid] = c_gt;
        vinc = c_gt;
        #pragma unroll
        for (int o = 1; o < 32; o <<= 1) {
            int n = __shfl_up_sync(0xffffffffu, vinc, o);
            if (lane >= o) vinc += n;
        }
        if (lane == 31) s_wsum[w] = vinc;
    } else if (tid < 320) {          // gt cell scan
        int c = tid - 256;
        cellv = s_gcnt[c];
        cellincl = cellv;
        #pragma unroll
        for (int o = 1; o < 32; o <<= 1) {
            int n = __shfl_up_sync(0xffffffffu, cellincl, o);
            if (lane >= o) cellincl += n;
        }
        if (lane == 31) s_ct[w - 8] = cellincl;   // idx 0,1
    } else if (tid < 384) {          // pred cell scan
        int c = tid - 320;
        cellv = s_pcnt[c];
        cellincl = cellv;
        #pragma unroll
        for (int o = 1; o < 32; o <<= 1) {
            int n = __shfl_up_sync(0xffffffffu, cellincl, o);
            if (lane >= o) cellincl += n;
        }
        if (lane == 31) s_ct[w - 8] = cellincl;   // idx 2,3
    } else if (tid < 640) {          // pred-track scan (warps 12-19)
        int c = tid - 384;
        prv = s_pr[c];
        princl = prv;
        #pragma unroll
        for (int o = 1; o < 32; o <<= 1) {
            int n = __shfl_up_sync(0xffffffffu, princl, o);
            if (lane >= o) princl += n;
        }
        if (lane == 31) s_wsum2[w - 12] = princl;
    }
    __syncthreads();
    if (tid < TT) {
        int woff = 0;
        #pragma unroll
        for (int k = 0; k < 8; k++) if (k < w) woff += s_wsum[k];
        int excl = woff + vinc - c_gt;
        s_toff[tid] = excl;
        s_tcur[tid] = 0;
        g_csr_off[b][tid] = excl;
    } else if (tid < 320) {
        int c = tid - 256;
        int excl = cellincl - cellv + ((c >= 32) ? s_ct[0] : 0);
        s_goffs[c] = excl;
        g_goff[b][c] = excl;
        if (c == 0) g_goff[b][NCELL] = MM;
    } else if (tid < 384) {
        int c = tid - 320;
        int excl = cellincl - cellv + ((c >= 32) ? s_ct[2] : 0);
        s_poffs[c] = excl;
    } else if (tid < 640) {
        int c = tid - 384;
        int woff = 0;
        int ww = w - 12;
        #pragma unroll
        for (int k = 0; k < 8; k++) if (k < ww) woff += s_wsum2[k];
        s_proff[c] = woff + princl - prv;
        s_prcur[c] = 0;
    }
    __syncthreads();

    // ---- phase 3a: deviations + pord + gt scatter ----
    #pragma unroll
    for (int k = 0; k < 2; k++) {
        int i = tid + k * 1024;
        int pk = s_p[i];
        int p = pk & 0xFF;
        int c = pk >> 8;
        if (p > 0) {
            atomicAdd(&s_dw[p], fabsf(s_w[i] - s_mw[p]));
            atomicAdd(&s_dh[p], fabsf(s_h[i] - s_mh[p]));
        }
        int pos = s_poffs[c] + atomicAdd(&s_pcur[c], 1);
        g_pord[b][pos] = i;
    }
    if (tid < MM) {
        int j = tid;
        float4 g = gb4[j];
        int t = gidb[j];
        int c = s_gcid[j];
        int pos = s_goffs[c] + atomicAdd(&s_gcur[c], 1);
        g_sgb[b][pos] = g;
        g_sa2[b][pos] = (s_pr[t] > 0) ? s_ga2[j] : F_INF;
        int tp = s_toff[t] + atomicAdd(&s_tcur[t], 1);
        g_csr[b][tp] = pos;                          // sorted position
    }
    __syncthreads();

    // ---- phase 3b: track-pred list scatter (aliases s_w; s_w/s_h dead now) ----
    int* tpl = (int*)s_w;
    #pragma unroll
    for (int k = 0; k < 2; k++) {
        int i = tid + k * 1024;
        int p = s_p[i] & 0xFF;
        if (p > 0) {
            int pos = s_proff[p] + atomicAdd(&s_prcur[p], 1);
            tpl[pos] = i;
        }
    }
    __syncthreads();

    // ---- phase 3c: temporal — WARP-PARALLEL per track (8 tracks per warp) ----
    float tp_acc = 0.f;
    {
        #pragma unroll
        for (int k = 0; k < 8; k++) {
            const int t = w * 8 + k;             // 0..255, warp-uniform
            if (t == 0) continue;
            const int cnt = s_pr[t];
            if (cnt <= 2) continue;
            const int off = s_proff[t];
            if (cnt <= 32) {
                // extraction sort via warp reduce-min (indices distinct)
                int rem = (lane < cnt) ? tpl[off + lane] : 0x7fffffff;
                int myidx = 0;
                for (int q = 0; q < cnt; q++) {
                    int m = __reduce_min_sync(0xffffffffu, rem);
                    if (rem == m) rem = 0x7fffffff;
                    if (lane == q) myidx = m;
                }
                // lane q holds q-th pred (original order); compute centers
                float cx = 0.f, cy = 0.f;
                if (lane < cnt) {
                    float4 bxx = pb4[myidx];
                    cx = (bxx.x + bxx.z) * 0.5f;
                    cy = (bxx.y + bxx.w) * 0.5f;
                }
                float c1x = __shfl_up_sync(0xffffffffu, cx, 1);
                float c1y = __shfl_up_sync(0xffffffffu, cy, 1);
                float c0x = __shfl_up_sync(0xffffffffu, cx, 2);
                float c0y = __shfl_up_sync(0xffffffffu, cy, 2);
                float sa_l = 0.f;
                if (lane >= 2 && lane < cnt) {
                    float ax = (cx - 2.f * c1x + c0x) * SCALE_C;
                    float ay = (cy - 2.f * c1y + c0y) * SCALE_C;
                    sa_l = sqrtf(ax * ax + ay * ay);
                }
                #pragma unroll
                for (int o = 16; o > 0; o >>= 1)
                    sa_l += __shfl_down_sync(0xffffffffu, sa_l, o);
                if (lane == 0) tp_acc += sa_l / (float)(cnt - 2);
            } else if (lane == 0) {
                // serial fallback (never hit with this data scale)
                for (int a = off + 1; a < off + cnt; a++) {
                    int key = tpl[a];
                    int q = a - 1;
                    while (q >= off && tpl[q] > key) { tpl[q + 1] = tpl[q]; q--; }
                    tpl[q + 1] = key;
                }
                float c0x = 0.f, c0y = 0.f, c1x = 0.f, c1y = 0.f;
                float sa = 0.f;
                for (int q = 0; q < cnt; q++) {
                    float4 bxx = pb4[tpl[off + q]];
                    float cx = (bxx.x + bxx.z) * 0.5f;
                    float cy = (bxx.y + bxx.w) * 0.5f;
                    if (q >= 2) {
                        float ax = (cx - 2.f * c1x + c0x) * SCALE_C;
                        float ay = (cy - 2.f * c1y + c0y) * SCALE_C;
                        sa += sqrtf(ax * ax + ay * ay);
                    }
                    c0x = c1x; c0y = c1y; c1x = cx; c1y = cy;
                }
                tp_acc += sa / (float)(cnt - 2);
            }
        }
    }

    // ---- phase 4: per-track terms + block reduce ----
    float fn = 0.f, sp = 0.f;
    int nu = 0;
    if (tid < TT) {
        int c  = s_pr[tid];
        int gc = s_gt[tid];
        fn = (gc > 0 && c == 0) ? (float)gc : 0.f;
        nu = (c > 0) ? 1 : 0;
        sp = (c > 1) ? (s_dw[tid] + s_dh[tid]) * SCALE_C / (float)c : 0.f;
    }
    #pragma unroll
    for (int o = 16; o > 0; o >>= 1) {
        fn     += __shfl_down_sync(0xffffffffu, fn, o);
        sp     += __shfl_down_sync(0xffffffffu, sp, o);
        nu     += __shfl_down_sync(0xffffffffu, nu, o);
        nvalid += __shfl_down_sync(0xffffffffu, nvalid, o);
    }
    if (lane == 0) { r_f[w] = fn; r_s[w] = sp; r_t[w] = tp_acc; r_u[w] = nu; r_v[w] = nvalid; }
    __syncthreads();
    if (tid == 0) {
        float F = 0.f, S = 0.f, T = 0.f; int U = 0, V = 0;
        #pragma unroll
        for (int k = 0; k < 32; k++) { F += r_f[k]; S += r_s[k]; T += r_t[k]; U += r_u[k]; V += r_v[k]; }
        g_fn[b] = F; g_nuni[b] = U; g_nvalid[b] = V;
        g_spatial[b] = (V > 1) ? S / fmaxf((float)U, 1.f) : 0.f;
        g_traw[b] = T;
    }
}

// ======================= K3: windowed IoU (SMEM) + match + finalize =======================
// grid (32, BB), 256 threads. 64 preds/block; 4 warp-groups stride the window j-loop.
__global__ __launch_bounds__(256) void k3_main(
    const float4* __restrict__ pboxes,
    const int*    __restrict__ pid,
    float* __restrict__ out)
{
    const int b = blockIdx.y;
    const int bx = blockIdx.x;
    const int tid = threadIdx.x;
    const int lane = tid & 31;

    __shared__ __align__(16) float4 s_gb[MM];   // sorted gt boxes  16 KB
    __shared__ __align__(16) float  s_a2[MM];   // sorted a2/INF     4 KB
    __shared__ int s_goff[NCELL + 1];
    __shared__ int s_last;

    const float4* __restrict__ sgbg = g_sgb[b];
    const float*  __restrict__ sa2g = g_sa2[b];
    #pragma unroll
    for (int k = 0; k < 4; k++) {
        int j = tid + k * 256;
        s_gb[j] = sgbg[j];
        s_a2[j] = sa2g[j];
    }
    if (tid < NCELL + 1) s_goff[tid] = g_goff[b][tid];
    __syncthreads();

    const int pred_l = tid & 63;
    const int msplit = tid >> 6;                 // warp-uniform (wid>>1)
    const int slot = bx * 64 + pred_l;
    const int idx = g_pord[b][slot];
    const int p = __ldg(&pid[b * NN + idx]);
    const float4 pbx = __ldg(&pboxes[b * NN + idx]);
    const float px1 = pbx.x, py1 = pbx.y, px2 = pbx.z, py2 = pbx.w;
    const float a1r = fmaxf(px2 - px1, 0.f) * fmaxf(py2 - py1, 0.f);
    const float a1 = (p > 0) ? a1r : F_INF;      // INF => hi-test always false

    // window cells (conservative: gt corner in [px1-102, px2] x [py1-102, py2])
    int cx0 = (int)(fmaxf(px1 - 103.f, 0.f) * CELL_SCALE);
    int cx1 = min((int)((px2 + 1.f) * CELL_SCALE), 7);
    int cy0 = (int)(fmaxf(py1 - 103.f, 0.f) * CELL_SCALE);
    int cy1 = min((int)((py2 + 1.f) * CELL_SCALE), 7);
    #pragma unroll
    for (int o = 16; o > 0; o >>= 1) {
        cx0 = min(cx0, __shfl_xor_sync(0xffffffffu, cx0, o));
        cx1 = max(cx1, __shfl_xor_sync(0xffffffffu, cx1, o));
        cy0 = min(cy0, __shfl_xor_sync(0xffffffffu, cy0, o));
        cy1 = max(cy1, __shfl_xor_sync(0xffffffffu, cy1, o));
    }

    int swc = 0;
    for (int cy = cy0; cy <= cy1; cy++) {
        const int rowb = cy * NCX;
        const int jlo = s_goff[rowb + cx0];
        const int jhi = s_goff[rowb + cx1 + 1];
        #pragma unroll 4
        for (int j = jlo + msplit; j < jhi; j += 4) {     // warp-uniform broadcast
            float4 g = s_gb[j];
            float a2 = s_a2[j];
            float lx = fmaxf(px1, g.x), ly = fmaxf(py1, g.y);
            float rx = fminf(px2, g.z), ry = fminf(py2, g.w);
            float inter = (rx - lx) * fmaxf(ry - ly, 0.f);   // single-clamp
            swc += (fmaf(3.f, inter, -a1) > a2);
        }
    }

    float matchv = 0.f, fpv = 0.f;
    if (msplit == 0 && p > 0) {
        int gc = g_gt_cnt[b][p];
        if (gc > 0) {
            int off = g_csr_off[b][p];
            float bn = 0.f, bd = 1.f;
            for (int k = 0; k < gc; k++) {
                int pos = g_csr[b][off + k];
                float4 g = s_gb[pos];
                float a2 = s_a2[pos];            // own track => finite
                float lx = fmaxf(px1, g.x), ly = fmaxf(py1, g.y);
                float rx = fminf(px2, g.z), ry = fminf(py2, g.w);
                float iw = rx - lx;
                float ihc = fmaxf(ry - ly, 0.f);
                float interh = iw * ihc;                       // identical hi-test
                swc -= (fmaf(3.f, interh, -a1) > a2);
                float inter = fmaxf(iw, 0.f) * ihc;            // true inter for IoU
                float uni = a1r + a2 - inter;
                if (inter * bd > bn * uni) { bn = inter; bd = uni; }
            }
            matchv = 1.f - __fdividef(bn, bd);
        } else {
            fpv = 1.f;
        }
    }

    #pragma unroll
    for (int o = 16; o > 0; o >>= 1) {
        matchv += __shfl_down_sync(0xffffffffu, matchv, o);
        fpv    += __shfl_down_sync(0xffffffffu, fpv, o);
        swc    += __shfl_down_sync(0xffffffffu, swc, o);
    }
    if (lane == 0) {
        atomicAdd(&g_match[b], matchv);
        atomicAdd(&g_fp[b], fpv);
        atomicAdd(&g_sw[b], swc);
    }

    // ---- last-block-done finalize ----
    __syncthreads();
    if (tid == 0) {
        __threadfence();
        int prev = atomicAdd(&g_done, 1);
        s_last = (prev == K3_TOTAL - 1) ? 1 : 0;
    }
    __syncthreads();
    if (s_last && tid < 32) {
        __threadfence();
        float lt = 0.f, ls = 0.f, lm = 0.f, nt = 0.f;
        if (tid < BB) {
            int bb = tid;
            int nv = g_nvalid[bb];
            int nu = g_nuni[bb];
            float has = (nv > 0) ? 1.f : 0.f;
            float mt  = *((volatile float*)&g_match[bb]);
            float fpb = *((volatile float*)&g_fp[bb]);
            int   sw  = *((volatile int*)&g_sw[bb]);
            float trw = g_traw[bb];
            float tr = B_FN * g_fn[bb] + mt + G_SW * (float)sw + B_FP * fpb;
            float tmp = (nv > 2) ? trw / fmaxf((float)nu, 1.f) : 0.f;
            lt = tr * has;
            ls = g_spatial[bb] * has;
            lm = tmp * has;
            nt = (float)nu * has;
        }
        #pragma unroll
        for (int o = 16; o > 0; o >>= 1) {
            lt += __shfl_down_sync(0xffffffffu, lt, o);
            ls += __shfl_down_sync(0xffffffffu, ls, o);
            lm += __shfl_down_sync(0xffffffffu, lm, o);
            nt += __shfl_down_sync(0xffffffffu, nt, o);
        }
        if (tid == 0) {
            float norm = (nt > 0.f) ? nt : 1.f;
            lt /= norm; ls /= norm; lm /= norm;
            out[0] = A_TRK * lt + A_SPA * ls + A_TMP * lm;
            out[1] = lt;
            out[2] = ls;
            out[3] = lm;
        }
    }
}

// ======================= launch =======================
extern "C" void kernel_launch(void* const* d_in, const int* in_sizes, int n_in,
                              void* d_out, int out_size)
{
    const float4* pb  = (const float4*)d_in[0];  // pred_boxes [16,2048,4] f32
    const float4* gb  = (const float4*)d_in[1];  // gt_boxes   [16,1024,4] f32
    const int*    pid = (const int*)d_in[2];     // pred_track_ids [16,2048] i32
    const int*    gid = (const int*)d_in[3];     // gt_track_ids   [16,1024] i32
    float* out = (float*)d_out;

    k1_prep<<<BB, 1024>>>(pb, gb, pid, gid);
    k3_main<<<dim3(K3_PB, BB), 256>>>(pb, pid, out);
}

// round 13
// speedup vs baseline: 1.3536x; 1.1671x over previous
#include <cuda_runtime.h>
#include <cstdint>

#define BB 16
#define NN 2048
#define MM 1024
#define TT 256

#define SCALE_C (4.5392368437151541e-04f)  // 1/sqrt(1920^2+1080^2)
#define A_TRK 2.0f
#define A_SPA 1.5f
#define A_TMP 1.8f
#define B_FP 0.9f
#define B_FN 0.9f
#define G_SW 1.5f

#define NCX 8
#define NCELL 64
#define CELL_SCALE 0.008f       // 1/125
#define F_INF __int_as_float(0x7f800000)

#define K3_SWEEP 32              // sweep blocks per batch (64 preds each)
#define K3_TEMP  8               // temporal blocks per batch
#define K3_BX (K3_SWEEP + K3_TEMP)          // 40
#define K3_TOTAL (K3_BX * BB)               // 640

// ---------------- device scratch (no allocations allowed) ----------------
__device__ int    g_gt_cnt[BB][TT];
__device__ int    g_pr_cnt[BB][TT];
__device__ int    g_csr_off[BB][TT];    // exclusive prefix of gt_cnt (track CSR)
__device__ int    g_csr[BB][MM];        // SORTED gt positions grouped by track id
__device__ float4 g_sgb[BB][MM];        // cell-sorted gt boxes
__device__ float  g_sa2[BB][MM];        // cell-sorted a2 (or +INF if track has no preds)
__device__ int    g_goff[BB][NCELL + 1];// gt cell CSR offsets
__device__ float4 g_spb[BB][NN];        // cell-sorted pred boxes
__device__ int    g_spid[BB][NN];       // cell-sorted pred ids
__device__ int    g_proff[BB][TT];      // pred-track CSR offsets
__device__ int    g_tpl[BB][NN];        // pred indices grouped by track (unordered)
__device__ float  g_fn[BB];
__device__ int    g_nuni[BB];
__device__ int    g_nvalid[BB];
__device__ float  g_match[BB];
__device__ float  g_fp[BB];
__device__ int    g_sw[BB];
__device__ float  g_spatial[BB];
__device__ float  g_traw[BB];
__device__ int    g_done;

// ======================= K1: hists + spatial + CSR builds =======================
__global__ __launch_bounds__(1024) void k1_prep(
    const float4* __restrict__ pboxes,
    const float4* __restrict__ gboxes,
    const int*    __restrict__ pid,
    const int*    __restrict__ gid)
{
    const int b = blockIdx.x;
    const int tid = threadIdx.x;
    const int lane = tid & 31, w = tid >> 5;

    __shared__ int   s_gt[TT], s_pr[TT];
    __shared__ float s_mw[TT], s_mh[TT], s_dw[TT], s_dh[TT];
    __shared__ int   s_toff[TT], s_tcur[TT];
    __shared__ int   s_proff[TT], s_prcur[TT];
    __shared__ float s_w[NN], s_h[NN];
    __shared__ int   s_p[NN];              // packed: pid | (cell<<8)
    __shared__ float s_ga2[MM];
    __shared__ int   s_gcid[MM];
    __shared__ int   s_gcnt[NCELL], s_goffs[NCELL], s_gcur[NCELL];
    __shared__ int   s_pcnt[NCELL], s_poffs[NCELL], s_pcur[NCELL];
    __shared__ int   s_wsum[8], s_wsum2[8];
    __shared__ int   s_ct[4];
    __shared__ float r_f[32], r_s[32];
    __shared__ int   r_u[32], r_v[32];

    if (tid < TT) {
        s_gt[tid] = 0; s_pr[tid] = 0;
        s_mw[tid] = 0.f; s_mh[tid] = 0.f;
        s_dw[tid] = 0.f; s_dh[tid] = 0.f;
    }
    if (tid < NCELL) {
        s_gcnt[tid] = 0; s_gcur[tid] = 0;
        s_pcnt[tid] = 0; s_pcur[tid] = 0;
    }
    if (b == 0 && tid == 0) g_done = 0;
    if (tid == 0) { g_match[b] = 0.f; g_fp[b] = 0.f; g_sw[b] = 0; g_traw[b] = 0.f; }
    __syncthreads();

    // ---- phase 1: histograms + stashes ----
    const int* gidb = gid + b * MM;
    const float4* gb4 = gboxes + b * MM;
    if (tid < MM) {
        float4 g = gb4[tid];
        int t = gidb[tid];
        float a2 = fmaxf(g.z - g.x, 0.f) * fmaxf(g.w - g.y, 0.f);
        int cx = min((int)(g.x * CELL_SCALE), 7);
        int cy = min((int)(g.y * CELL_SCALE), 7);
        int c = cy * NCX + cx;
        s_ga2[tid] = a2;
        s_gcid[tid] = c;
        atomicAdd(&s_gt[t], 1);
        atomicAdd(&s_gcnt[c], 1);
    }
    const int* pidb = pid + b * NN;
    const float4* pb4 = pboxes + b * NN;
    int nvalid = 0;
    #pragma unroll
    for (int k = 0; k < 2; k++) {
        int i = tid + k * 1024;
        int p = pidb[i];
        float4 bx = pb4[i];
        float bw = bx.z - bx.x, bh = bx.w - bx.y;
        int cx = min((int)(bx.x * CELL_SCALE), 7);
        int cy = min((int)(bx.y * CELL_SCALE), 7);
        int c = cy * NCX + cx;
        s_w[i] = bw; s_h[i] = bh;
        s_p[i] = p | (c << 8);             // pid in [0,255]
        atomicAdd(&s_pcnt[c], 1);
        if (p > 0) {
            atomicAdd(&s_pr[p], 1);
            atomicAdd(&s_mw[p], bw);
            atomicAdd(&s_mh[p], bh);
            nvalid++;
        }
    }
    __syncthreads();

    // ---- phase 2: 4 prefix scans ----
    int c_gt = 0, vinc = 0;
    int cellv = 0, cellincl = 0;
    int prv = 0, princl = 0;
    if (tid < TT) {
        int c = s_pr[tid];
        float cs = fmaxf((float)c, 1.f);
        s_mw[tid] = s_mw[tid] / cs;
        s_mh[tid] = s_mh[tid] / cs;
        g_pr_cnt[b][tid] = c;
        c_gt = s_gt[tid];
        g_gt_cnt[b][tid] = c_gt;
        vinc = c_gt;
        #pragma unroll
        for (int o = 1; o < 32; o <<= 1) {
            int n = __shfl_up_sync(0xffffffffu, vinc, o);
            if (lane >= o) vinc += n;
        }
        if (lane == 31) s_wsum[w] = vinc;
    } else if (tid < 320) {          // gt cell scan
        int c = tid - 256;
        cellv = s_gcnt[c];
        cellincl = cellv;
        #pragma unroll
        for (int o = 1; o < 32; o <<= 1) {
            int n = __shfl_up_sync(0xffffffffu, cellincl, o);
            if (lane >= o) cellincl += n;
        }
        if (lane == 31) s_ct[w - 8] = cellincl;   // idx 0,1
    } else if (tid < 384) {          // pred cell scan
        int c = tid - 320;
        cellv = s_pcnt[c];
        cellincl = cellv;
        #pragma unroll
        for (int o = 1; o < 32; o <<= 1) {
            int n = __shfl_up_sync(0xffffffffu, cellincl, o);
            if (lane >= o) cellincl += n;
        }
        if (lane == 31) s_ct[w - 8] = cellincl;   // idx 2,3
    } else if (tid < 640) {          // pred-track scan (warps 12-19)
        int c = tid - 384;
        prv = s_pr[c];
        princl = prv;
        #pragma unroll
        for (int o = 1; o < 32; o <<= 1) {
            int n = __shfl_up_sync(0xffffffffu, princl, o);
            if (lane >= o) princl += n;
        }
        if (lane == 31) s_wsum2[w - 12] = princl;
    }
    __syncthreads();
    if (tid < TT) {
        int woff = 0;
        #pragma unroll
        for (int k = 0; k < 8; k++) if (k < w) woff += s_wsum[k];
        int excl = woff + vinc - c_gt;
        s_toff[tid] = excl;
        s_tcur[tid] = 0;
        g_csr_off[b][tid] = excl;
    } else if (tid < 320) {
        int c = tid - 256;
        int excl = cellincl - cellv + ((c >= 32) ? s_ct[0] : 0);
        s_goffs[c] = excl;
        g_goff[b][c] = excl;
        if (c == 0) g_goff[b][NCELL] = MM;
    } else if (tid < 384) {
        int c = tid - 320;
        int excl = cellincl - cellv + ((c >= 32) ? s_ct[2] : 0);
        s_poffs[c] = excl;
    } else if (tid < 640) {
        int c = tid - 384;
        int woff = 0;
        int ww = w - 12;
        #pragma unroll
        for (int k = 0; k < 8; k++) if (k < ww) woff += s_wsum2[k];
        int excl = woff + princl - prv;
        s_proff[c] = excl;
        s_prcur[c] = 0;
        g_proff[b][c] = excl;
    }
    __syncthreads();

    // ---- phase 3: deviations + all scatters ----
    #pragma unroll
    for (int k = 0; k < 2; k++) {
        int i = tid + k * 1024;
        int pk = s_p[i];
        int p = pk & 0xFF;
        int c = pk >> 8;
        float4 bx = pb4[i];                // L1-resident reload
        if (p > 0) {
            atomicAdd(&s_dw[p], fabsf(s_w[i] - s_mw[p]));
            atomicAdd(&s_dh[p], fabsf(s_h[i] - s_mh[p]));
            int tp = s_proff[p] + atomicAdd(&s_prcur[p], 1);
            g_tpl[b][tp] = i;
        }
        int pos = s_poffs[c] + atomicAdd(&s_pcur[c], 1);
        g_spb[b][pos] = bx;
        g_spid[b][pos] = p;
    }
    if (tid < MM) {
        int j = tid;
        float4 g = gb4[j];
        int t = gidb[j];
        int c = s_gcid[j];
        int pos = s_goffs[c] + atomicAdd(&s_gcur[c], 1);
        g_sgb[b][pos] = g;
        g_sa2[b][pos] = (s_pr[t] > 0) ? s_ga2[j] : F_INF;
        int tp = s_toff[t] + atomicAdd(&s_tcur[t], 1);
        g_csr[b][tp] = pos;                          // sorted position
    }
    __syncthreads();

    // ---- phase 4: per-track terms + block reduce ----
    float fn = 0.f, sp = 0.f;
    int nu = 0;
    if (tid < TT) {
        int c  = s_pr[tid];
        int gc = s_gt[tid];
        fn = (gc > 0 && c == 0) ? (float)gc : 0.f;
        nu = (c > 0) ? 1 : 0;
        sp = (c > 1) ? (s_dw[tid] + s_dh[tid]) * SCALE_C / (float)c : 0.f;
    }
    #pragma unroll
    for (int o = 16; o > 0; o >>= 1) {
        fn     += __shfl_down_sync(0xffffffffu, fn, o);
        sp     += __shfl_down_sync(0xffffffffu, sp, o);
        nu     += __shfl_down_sync(0xffffffffu, nu, o);
        nvalid += __shfl_down_sync(0xffffffffu, nvalid, o);
    }
    if (lane == 0) { r_f[w] = fn; r_s[w] = sp; r_u[w] = nu; r_v[w] = nvalid; }
    __syncthreads();
    if (tid == 0) {
        float F = 0.f, S = 0.f; int U = 0, V = 0;
        #pragma unroll
        for (int k = 0; k < 32; k++) { F += r_f[k]; S += r_s[k]; U += r_u[k]; V += r_v[k]; }
        g_fn[b] = F; g_nuni[b] = U; g_nvalid[b] = V;
        g_spatial[b] = (V > 1) ? S / fmaxf((float)U, 1.f) : 0.f;
    }
}

// ======================= K3: sweep blocks + temporal blocks + finalize =======================
// grid (40, BB), 256 threads. bx<32: 64 preds/block, 4-way msplit sweep.
// bx>=32: temporal, 8 warps x 4 tracks each.
__global__ __launch_bounds__(256) void k3_main(
    const float4* __restrict__ pboxes,
    float* __restrict__ out)
{
    const int b = blockIdx.y;
    const int bx = blockIdx.x;
    const int tid = threadIdx.x;
    const int lane = tid & 31;
    const int wid = tid >> 5;

    __shared__ __align__(16) float4 s_gb[MM];   // sorted gt boxes  16 KB
    __shared__ __align__(16) float  s_a2[MM];   // sorted a2/INF     4 KB
    __shared__ int   s_goff[NCELL + 1];
    __shared__ float sm_m[4], sm_f[4];
    __shared__ int   sm_s[4];
    __shared__ int   s_tsort[8][33];
    __shared__ int   s_last;

    if (bx < K3_SWEEP) {
        // ================= SWEEP BLOCK =================
        const float4* __restrict__ sgbg = g_sgb[b];
        const float*  __restrict__ sa2g = g_sa2[b];
        #pragma unroll
        for (int k = 0; k < 4; k++) {
            int j = tid + k * 256;
            s_gb[j] = sgbg[j];
            s_a2[j] = sa2g[j];
        }
        if (tid < NCELL + 1) s_goff[tid] = g_goff[b][tid];
        __syncthreads();

        const int pred_l = tid & 63;
        const int msplit = tid >> 6;                 // warp-uniform (wid>>1)
        const int slot = bx * 64 + pred_l;
        const int p = g_spid[b][slot];               // coalesced
        const float4 pbx = g_spb[b][slot];           // coalesced
        const float px1 = pbx.x, py1 = pbx.y, px2 = pbx.z, py2 = pbx.w;
        const float a1r = fmaxf(px2 - px1, 0.f) * fmaxf(py2 - py1, 0.f);
        const float a1 = (p > 0) ? a1r : F_INF;      // INF => hi-test always false

        // window cells (conservative: gt corner in [px1-102, px2] x [py1-102, py2])
        int cx0 = (int)(fmaxf(px1 - 103.f, 0.f) * CELL_SCALE);
        int cx1 = min((int)((px2 + 1.f) * CELL_SCALE), 7);
        int cy0 = (int)(fmaxf(py1 - 103.f, 0.f) * CELL_SCALE);
        int cy1 = min((int)((py2 + 1.f) * CELL_SCALE), 7);
        #pragma unroll
        for (int o = 16; o > 0; o >>= 1) {
            cx0 = min(cx0, __shfl_xor_sync(0xffffffffu, cx0, o));
            cx1 = max(cx1, __shfl_xor_sync(0xffffffffu, cx1, o));
            cy0 = min(cy0, __shfl_xor_sync(0xffffffffu, cy0, o));
            cy1 = max(cy1, __shfl_xor_sync(0xffffffffu, cy1, o));
        }

        int swc = 0;
        for (int cy = cy0; cy <= cy1; cy++) {
            const int rowb = cy * NCX;
            const int jlo = s_goff[rowb + cx0];
            const int jhi = s_goff[rowb + cx1 + 1];
            #pragma unroll 4
            for (int j = jlo + msplit; j < jhi; j += 4) {     // warp-uniform broadcast
                float4 g = s_gb[j];
                float a2 = s_a2[j];
                float lx = fmaxf(px1, g.x), ly = fmaxf(py1, g.y);
                float rx = fminf(px2, g.z), ry = fminf(py2, g.w);
                float inter = (rx - lx) * fmaxf(ry - ly, 0.f);   // single-clamp
                swc += (fmaf(3.f, inter, -a1) > a2);
            }
        }

        float matchv = 0.f, fpv = 0.f;
        if (msplit == 0 && p > 0) {
            int gc = g_gt_cnt[b][p];
            if (gc > 0) {
                int off = g_csr_off[b][p];
                float bn = 0.f, bd = 1.f;
                for (int k = 0; k < gc; k++) {
                    int pos = g_csr[b][off + k];
                    float4 g = s_gb[pos];
                    float a2 = s_a2[pos];            // own track => finite
                    float lx = fmaxf(px1, g.x), ly = fmaxf(py1, g.y);
                    float rx = fminf(px2, g.z), ry = fminf(py2, g.w);
                    float iw = rx - lx;
                    float ihc = fmaxf(ry - ly, 0.f);
                    float interh = iw * ihc;                       // identical hi-test
                    swc -= (fmaf(3.f, interh, -a1) > a2);
                    float inter = fmaxf(iw, 0.f) * ihc;            // true inter for IoU
                    float uni = a1r + a2 - inter;
                    if (inter * bd > bn * uni) { bn = inter; bd = uni; }
                }
                matchv = 1.f - __fdividef(bn, bd);
            } else {
                fpv = 1.f;
            }
        }

        // warp reduce; combine halves in smem; one atomic set per block
        #pragma unroll
        for (int o = 16; o > 0; o >>= 1) {
            matchv += __shfl_down_sync(0xffffffffu, matchv, o);
            fpv    += __shfl_down_sync(0xffffffffu, fpv, o);
            swc    += __shfl_down_sync(0xffffffffu, swc, o);
        }
        if (lane == 0) {
            if (wid & 1) {     // odd warps only carry swc
                atomicAdd(&sm_s[wid >> 1], 0);   // placeholder keep layout
            }
        }
        __syncthreads();       // ensure sm arrays initialized order... (init below instead)
        if (tid < 4) { sm_m[tid] = 0.f; sm_f[tid] = 0.f; sm_s[tid] = 0; }
        __syncthreads();
        if (lane == 0) {
            atomicAdd(&sm_m[0], matchv);
            atomicAdd(&sm_f[0], fpv);
            atomicAdd(&sm_s[0], swc);
        }
        __syncthreads();
        if (tid == 0) {
            atomicAdd(&g_match[b], sm_m[0]);
            atomicAdd(&g_fp[b], sm_f[0]);
            atomicAdd(&g_sw[b], sm_s[0]);
        }
    } else {
        // ================= TEMPORAL BLOCK =================
        const float4* pb4 = pboxes + b * NN;
        const int tw = (bx - K3_SWEEP) * 8 + wid;    // 0..63
        float tsum = 0.f;
        #pragma unroll
        for (int k = 0; k < 4; k++) {
            const int t = tw * 4 + k;                // 0..255, warp-uniform
            if (t == 0) continue;
            const int cnt = g_pr_cnt[b][t];
            if (cnt <= 2) continue;
            const int off = g_proff[b][t];
            if (cnt <= 32) {
                int v = (lane < cnt) ? g_tpl[b][off + lane] : 0x7fffffff;
                int rank = 0;
                for (int o = 1; o < cnt; o++) {
                    int src = lane + o;
                    if (src >= cnt) src -= cnt;
                    int ov = __shfl_sync(0xffffffffu, v, src);
                    rank += (ov < v);
                }
                if (lane < cnt) s_tsort[wid][rank] = v;
                __syncwarp();
                int myidx = (lane < cnt) ? s_tsort[wid][lane] : 0;
                float cx = 0.f, cy = 0.f;
                if (lane < cnt) {
                    float4 bxx = pb4[myidx];
                    cx = (bxx.x + bxx.z) * 0.5f;
                    cy = (bxx.y + bxx.w) * 0.5f;
                }
                float c1x = __shfl_up_sync(0xffffffffu, cx, 1);
                float c1y = __shfl_up_sync(0xffffffffu, cy, 1);
                float c0x = __shfl_up_sync(0xffffffffu, cx, 2);
                float c0y = __shfl_up_sync(0xffffffffu, cy, 2);
                float sa_l = 0.f;
                if (lane >= 2 && lane < cnt) {
                    float ax = (cx - 2.f * c1x + c0x) * SCALE_C;
                    float ay = (cy - 2.f * c1y + c0y) * SCALE_C;
                    sa_l = sqrtf(ax * ax + ay * ay);
                }
                #pragma unroll
                for (int o = 16; o > 0; o >>= 1)
                    sa_l += __shfl_down_sync(0xffffffffu, sa_l, o);
                if (lane == 0) tsum += sa_l / (float)(cnt - 2);
            } else if (lane == 0) {
                // serial fallback (data scale never hits this)
                int last = -1;
                float c0x = 0.f, c0y = 0.f, c1x = 0.f, c1y = 0.f;
                float sa = 0.f;
                for (int q = 0; q < cnt; q++) {
                    int m = 0x7fffffff;
                    for (int a = 0; a < cnt; a++) {
                        int vv = g_tpl[b][off + a];
                        if (vv > last && vv < m) m = vv;
                    }
                    last = m;
                    float4 bxx = pb4[m];
                    float cx = (bxx.x + bxx.z) * 0.5f;
                    float cy = (bxx.y + bxx.w) * 0.5f;
                    if (q >= 2) {
                        float ax = (cx - 2.f * c1x + c0x) * SCALE_C;
                        float ay = (cy - 2.f * c1y + c0y) * SCALE_C;
                        sa += sqrtf(ax * ax + ay * ay);
                    }
                    c0x = c1x; c0y = c1y; c1x = cx; c1y = cy;
                }
                tsum += sa / (float)(cnt - 2);
            }
        }
        if (lane == 0 && tsum != 0.f)
            atomicAdd(&g_traw[b], tsum);
    }

    // ---- last-block-done finalize ----
    __syncthreads();
    if (tid == 0) {
        __threadfence();
        int prev = atomicAdd(&g_done, 1);
        s_last = (prev == K3_TOTAL - 1) ? 1 : 0;
    }
    __syncthreads();
    if (s_last && tid < 32) {
        __threadfence();
        float lt = 0.f, ls = 0.f, lm = 0.f, nt = 0.f;
        if (tid < BB) {
            int bb = tid;
            int nv = g_nvalid[bb];
            int nu = g_nuni[bb];
            float has = (nv > 0) ? 1.f : 0.f;
            float mt  = *((volatile float*)&g_match[bb]);
            float fpb = *((volatile float*)&g_fp[bb]);
            int   sw  = *((volatile int*)&g_sw[bb]);
            float trw = *((volatile float*)&g_traw[bb]);
            float tr = B_FN * g_fn[bb] + mt + G_SW * (float)sw + B_FP * fpb;
            float tmp = (nv > 2) ? trw / fmaxf((float)nu, 1.f) : 0.f;
            lt = tr * has;
            ls = g_spatial[bb] * has;
            lm = tmp * has;
            nt = (float)nu * has;
        }
        #pragma unroll
        for (int o = 16; o > 0; o >>= 1) {
            lt += __shfl_down_sync(0xffffffffu, lt, o);
            ls += __shfl_down_sync(0xffffffffu, ls, o);
            lm += __shfl_down_sync(0xffffffffu, lm, o);
            nt += __shfl_down_sync(0xffffffffu, nt, o);
        }
        if (tid == 0) {
            float norm = (nt > 0.f) ? nt : 1.f;
            lt /= norm; ls /= norm; lm /= norm;
            out[0] = A_TRK * lt + A_SPA * ls + A_TMP * lm;
            out[1] = lt;
            out[2] = ls;
            out[3] = lm;
        }
    }
}

// ======================= launch =======================
extern "C" void kernel_launch(void* const* d_in, const int* in_sizes, int n_in,
                              void* d_out, int out_size)
{
    const float4* pb  = (const float4*)d_in[0];  // pred_boxes [16,2048,4] f32
    const float4* gb  = (const float4*)d_in[1];  // gt_boxes   [16,1024,4] f32
    const int*    pid = (const int*)d_in[2];     // pred_track_ids [16,2048] i32
    const int*    gid = (const int*)d_in[3];     // gt_track_ids   [16,1024] i32
    float* out = (float*)d_out;

    k1_prep<<<BB, 1024>>>(pb, gb, pid, gid);
    k3_main<<<dim3(K3_BX, BB), 256>>>(pb, out);
}

// round 14
// speedup vs baseline: 1.4518x; 1.0725x over previous
#include <cuda_runtime.h>
#include <cstdint>

#define BB 16
#define NN 2048
#define MM 1024
#define TT 256

#define SCALE_C (4.5392368437151541e-04f)  // 1/sqrt(1920^2+1080^2)
#define A_TRK 2.0f
#define A_SPA 1.5f
#define A_TMP 1.8f
#define B_FP 0.9f
#define B_FN 0.9f
#define G_SW 1.5f

#define NCX 8
#define NCELL 64
#define CELL_SCALE 0.008f       // 1/125
#define F_INF __int_as_float(0x7f800000)

#define K3_SWEEP 32              // sweep blocks per batch (64 preds each)
#define K3_TEMP  5               // temporal blocks per batch
#define K3_BX (K3_SWEEP + K3_TEMP)          // 37
#define K3_TOTAL (K3_BX * BB)               // 592 = 4 * 148 (no partial wave)

// ---------------- device scratch (no allocations allowed) ----------------
__device__ int    g_gt_cnt[BB][TT];
__device__ int    g_pr_cnt[BB][TT];
__device__ int    g_csr_off[BB][TT];    // exclusive prefix of gt_cnt (track CSR)
__device__ int    g_csr[BB][MM];        // SORTED gt positions grouped by track id
__device__ float4 g_sgb[BB][MM];        // cell-sorted gt boxes
__device__ float  g_sa2[BB][MM];        // cell-sorted a2 (or +INF if track has no preds)
__device__ int    g_goff[BB][NCELL + 1];// gt cell CSR offsets
__device__ float4 g_spb[BB][NN];        // cell-sorted pred boxes
__device__ int    g_spid[BB][NN];       // cell-sorted pred ids
__device__ int    g_proff[BB][TT];      // pred-track CSR offsets
__device__ int    g_tpl[BB][NN];        // pred indices grouped by track (unordered)
__device__ float  g_fn[BB];
__device__ int    g_nuni[BB];
__device__ int    g_nvalid[BB];
__device__ float  g_match[BB];
__device__ float  g_fp[BB];
__device__ int    g_sw[BB];
__device__ float  g_spatial[BB];
__device__ float  g_traw[BB];
__device__ int    g_done;

// ======================= K1: hists + spatial + CSR builds =======================
__global__ __launch_bounds__(1024) void k1_prep(
    const float4* __restrict__ pboxes,
    const float4* __restrict__ gboxes,
    const int*    __restrict__ pid,
    const int*    __restrict__ gid)
{
    const int b = blockIdx.x;
    const int tid = threadIdx.x;
    const int lane = tid & 31, w = tid >> 5;

    __shared__ int   s_gt[TT], s_pr[TT];
    __shared__ float s_mw[TT], s_mh[TT], s_dw[TT], s_dh[TT];
    __shared__ int   s_toff[TT], s_tcur[TT];
    __shared__ int   s_proff[TT], s_prcur[TT];
    __shared__ float s_w[NN], s_h[NN];
    __shared__ int   s_p[NN];              // packed: pid | (cell<<8)
    __shared__ float s_ga2[MM];
    __shared__ int   s_gcid[MM];
    __shared__ int   s_gcnt[NCELL], s_goffs[NCELL], s_gcur[NCELL];
    __shared__ int   s_pcnt[NCELL], s_poffs[NCELL], s_pcur[NCELL];
    __shared__ int   s_wsum[8], s_wsum2[8];
    __shared__ int   s_ct[4];
    __shared__ float r_f[32], r_s[32];
    __shared__ int   r_u[32], r_v[32];

    if (tid < TT) {
        s_gt[tid] = 0; s_pr[tid] = 0;
        s_mw[tid] = 0.f; s_mh[tid] = 0.f;
        s_dw[tid] = 0.f; s_dh[tid] = 0.f;
    }
    if (tid < NCELL) {
        s_gcnt[tid] = 0; s_gcur[tid] = 0;
        s_pcnt[tid] = 0; s_pcur[tid] = 0;
    }
    if (b == 0 && tid == 0) g_done = 0;
    if (tid == 0) { g_match[b] = 0.f; g_fp[b] = 0.f; g_sw[b] = 0; g_traw[b] = 0.f; }
    __syncthreads();

    // ---- phase 1: histograms + stashes ----
    const int* gidb = gid + b * MM;
    const float4* gb4 = gboxes + b * MM;
    if (tid < MM) {
        float4 g = gb4[tid];
        int t = gidb[tid];
        float a2 = fmaxf(g.z - g.x, 0.f) * fmaxf(g.w - g.y, 0.f);
        int cx = min((int)(g.x * CELL_SCALE), 7);
        int cy = min((int)(g.y * CELL_SCALE), 7);
        int c = cy * NCX + cx;
        s_ga2[tid] = a2;
        s_gcid[tid] = c;
        atomicAdd(&s_gt[t], 1);
        atomicAdd(&s_gcnt[c], 1);
    }
    const int* pidb = pid + b * NN;
    const float4* pb4 = pboxes + b * NN;
    int nvalid = 0;
    #pragma unroll
    for (int k = 0; k < 2; k++) {
        int i = tid + k * 1024;
        int p = pidb[i];
        float4 bx = pb4[i];
        float bw = bx.z - bx.x, bh = bx.w - bx.y;
        int cx = min((int)(bx.x * CELL_SCALE), 7);
        int cy = min((int)(bx.y * CELL_SCALE), 7);
        int c = cy * NCX + cx;
        s_w[i] = bw; s_h[i] = bh;
        s_p[i] = p | (c << 8);             // pid in [0,255]
        atomicAdd(&s_pcnt[c], 1);
        if (p > 0) {
            atomicAdd(&s_pr[p], 1);
            atomicAdd(&s_mw[p], bw);
            atomicAdd(&s_mh[p], bh);
            nvalid++;
        }
    }
    __syncthreads();

    // ---- phase 2: 4 prefix scans ----
    int c_gt = 0, vinc = 0;
    int cellv = 0, cellincl = 0;
    int prv = 0, princl = 0;
    if (tid < TT) {
        int c = s_pr[tid];
        float cs = fmaxf((float)c, 1.f);
        s_mw[tid] = s_mw[tid] / cs;
        s_mh[tid] = s_mh[tid] / cs;
        g_pr_cnt[b][tid] = c;
        c_gt = s_gt[tid];
        g_gt_cnt[b][tid] = c_gt;
        vinc = c_gt;
        #pragma unroll
        for (int o = 1; o < 32; o <<= 1) {
            int n = __shfl_up_sync(0xffffffffu, vinc, o);
            if (lane >= o) vinc += n;
        }
        if (lane == 31) s_wsum[w] = vinc;
    } else if (tid < 320) {          // gt cell scan
        int c = tid - 256;
        cellv = s_gcnt[c];
        cellincl = cellv;
        #pragma unroll
        for (int o = 1; o < 32; o <<= 1) {
            int n = __shfl_up_sync(0xffffffffu, cellincl, o);
            if (lane >= o) cellincl += n;
        }
        if (lane == 31) s_ct[w - 8] = cellincl;   // idx 0,1
    } else if (tid < 384) {          // pred cell scan
        int c = tid - 320;
        cellv = s_pcnt[c];
        cellincl = cellv;
        #pragma unroll
        for (int o = 1; o < 32; o <<= 1) {
            int n = __shfl_up_sync(0xffffffffu, cellincl, o);
            if (lane >= o) cellincl += n;
        }
        if (lane == 31) s_ct[w - 8] = cellincl;   // idx 2,3
    } else if (tid < 640) {          // pred-track scan (warps 12-19)
        int c = tid - 384;
        prv = s_pr[c];
        princl = prv;
        #pragma unroll
        for (int o = 1; o < 32; o <<= 1) {
            int n = __shfl_up_sync(0xffffffffu, princl, o);
            if (lane >= o) princl += n;
        }
        if (lane == 31) s_wsum2[w - 12] = princl;
    }
    __syncthreads();
    if (tid < TT) {
        int woff = 0;
        #pragma unroll
        for (int k = 0; k < 8; k++) if (k < w) woff += s_wsum[k];
        int excl = woff + vinc - c_gt;
        s_toff[tid] = excl;
        s_tcur[tid] = 0;
        g_csr_off[b][tid] = excl;
    } else if (tid < 320) {
        int c = tid - 256;
        int excl = cellincl - cellv + ((c >= 32) ? s_ct[0] : 0);
        s_goffs[c] = excl;
        g_goff[b][c] = excl;
        if (c == 0) g_goff[b][NCELL] = MM;
    } else if (tid < 384) {
        int c = tid - 320;
        int excl = cellincl - cellv + ((c >= 32) ? s_ct[2] : 0);
        s_poffs[c] = excl;
    } else if (tid < 640) {
        int c = tid - 384;
        int woff = 0;
        int ww = w - 12;
        #pragma unroll
        for (int k = 0; k < 8; k++) if (k < ww) woff += s_wsum2[k];
        int excl = woff + princl - prv;
        s_proff[c] = excl;
        s_prcur[c] = 0;
        g_proff[b][c] = excl;
    }
    __syncthreads();

    // ---- phase 3: deviations + all scatters ----
    #pragma unroll
    for (int k = 0; k < 2; k++) {
        int i = tid + k * 1024;
        int pk = s_p[i];
        int p = pk & 0xFF;
        int c = pk >> 8;
        float4 bx = pb4[i];                // L1-resident reload
        if (p > 0) {
            atomicAdd(&s_dw[p], fabsf(s_w[i] - s_mw[p]));
            atomicAdd(&s_dh[p], fabsf(s_h[i] - s_mh[p]));
            int tp = s_proff[p] + atomicAdd(&s_prcur[p], 1);
            g_tpl[b][tp] = i;
        }
        int pos = s_poffs[c] + atomicAdd(&s_pcur[c], 1);
        g_spb[b][pos] = bx;
        g_spid[b][pos] = p;
    }
    if (tid < MM) {
        int j = tid;
        float4 g = gb4[j];
        int t = gidb[j];
        int c = s_gcid[j];
        int pos = s_goffs[c] + atomicAdd(&s_gcur[c], 1);
        g_sgb[b][pos] = g;
        g_sa2[b][pos] = (s_pr[t] > 0) ? s_ga2[j] : F_INF;
        int tp = s_toff[t] + atomicAdd(&s_tcur[t], 1);
        g_csr[b][tp] = pos;                          // sorted position
    }
    __syncthreads();

    // ---- phase 4: per-track terms + block reduce ----
    float fn = 0.f, sp = 0.f;
    int nu = 0;
    if (tid < TT) {
        int c  = s_pr[tid];
        int gc = s_gt[tid];
        fn = (gc > 0 && c == 0) ? (float)gc : 0.f;
        nu = (c > 0) ? 1 : 0;
        sp = (c > 1) ? (s_dw[tid] + s_dh[tid]) * SCALE_C / (float)c : 0.f;
    }
    #pragma unroll
    for (int o = 16; o > 0; o >>= 1) {
        fn     += __shfl_down_sync(0xffffffffu, fn, o);
        sp     += __shfl_down_sync(0xffffffffu, sp, o);
        nu     += __shfl_down_sync(0xffffffffu, nu, o);
        nvalid += __shfl_down_sync(0xffffffffu, nvalid, o);
    }
    if (lane == 0) { r_f[w] = fn; r_s[w] = sp; r_u[w] = nu; r_v[w] = nvalid; }
    __syncthreads();
    if (tid == 0) {
        float F = 0.f, S = 0.f; int U = 0, V = 0;
        #pragma unroll
        for (int k = 0; k < 32; k++) { F += r_f[k]; S += r_s[k]; U += r_u[k]; V += r_v[k]; }
        g_fn[b] = F; g_nuni[b] = U; g_nvalid[b] = V;
        g_spatial[b] = (V > 1) ? S / fmaxf((float)U, 1.f) : 0.f;
    }
}

// ======================= K3: sweep blocks + temporal blocks + finalize =======================
// grid (37, BB), 256 threads. bx<32: 64 preds/block, 4-way msplit sweep.
// bx>=32: temporal, 8 warps x 7 tracks each (40 warps cover 256 tracks).
__global__ __launch_bounds__(256) void k3_main(
    const float4* __restrict__ pboxes,
    float* __restrict__ out)
{
    const int b = blockIdx.y;
    const int bx = blockIdx.x;
    const int tid = threadIdx.x;
    const int lane = tid & 31;
    const int wid = tid >> 5;

    __shared__ __align__(16) float4 s_gb[MM];   // sorted gt boxes  16 KB
    __shared__ __align__(16) float  s_a2[MM];   // sorted a2/INF     4 KB
    __shared__ int   s_goff[NCELL + 1];
    __shared__ float sm_m, sm_f;
    __shared__ int   sm_s;
    __shared__ int   s_tsort[8][33];
    __shared__ int   s_last;

    if (bx < K3_SWEEP) {
        // ================= SWEEP BLOCK =================
        const float4* __restrict__ sgbg = g_sgb[b];
        const float*  __restrict__ sa2g = g_sa2[b];
        #pragma unroll
        for (int k = 0; k < 4; k++) {
            int j = tid + k * 256;
            s_gb[j] = sgbg[j];
            s_a2[j] = sa2g[j];
        }
        if (tid < NCELL + 1) s_goff[tid] = g_goff[b][tid];
        if (tid == 0) { sm_m = 0.f; sm_f = 0.f; sm_s = 0; }
        __syncthreads();

        const int pred_l = tid & 63;
        const int msplit = tid >> 6;                 // warp-uniform (wid>>1)
        const int slot = bx * 64 + pred_l;
        const int p = g_spid[b][slot];               // coalesced
        const float4 pbx = g_spb[b][slot];           // coalesced
        const float px1 = pbx.x, py1 = pbx.y, px2 = pbx.z, py2 = pbx.w;
        const float a1r = fmaxf(px2 - px1, 0.f) * fmaxf(py2 - py1, 0.f);
        const float a1 = (p > 0) ? a1r : F_INF;      // INF => hi-test always false

        // window cells (conservative: gt corner in [px1-102, px2] x [py1-102, py2])
        int cx0 = (int)(fmaxf(px1 - 103.f, 0.f) * CELL_SCALE);
        int cx1 = min((int)((px2 + 1.f) * CELL_SCALE), 7);
        int cy0 = (int)(fmaxf(py1 - 103.f, 0.f) * CELL_SCALE);
        int cy1 = min((int)((py2 + 1.f) * CELL_SCALE), 7);
        #pragma unroll
        for (int o = 16; o > 0; o >>= 1) {
            cx0 = min(cx0, __shfl_xor_sync(0xffffffffu, cx0, o));
            cx1 = max(cx1, __shfl_xor_sync(0xffffffffu, cx1, o));
            cy0 = min(cy0, __shfl_xor_sync(0xffffffffu, cy0, o));
            cy1 = max(cy1, __shfl_xor_sync(0xffffffffu, cy1, o));
        }

        int swc = 0;
        for (int cy = cy0; cy <= cy1; cy++) {
            const int rowb = cy * NCX;
            const int jlo = s_goff[rowb + cx0];
            const int jhi = s_goff[rowb + cx1 + 1];
            #pragma unroll 4
            for (int j = jlo + msplit; j < jhi; j += 4) {     // warp-uniform broadcast
                float4 g = s_gb[j];
                float a2 = s_a2[j];
                float lx = fmaxf(px1, g.x), ly = fmaxf(py1, g.y);
                float rx = fminf(px2, g.z), ry = fminf(py2, g.w);
                float inter = (rx - lx) * fmaxf(ry - ly, 0.f);   // single-clamp
                swc += (fmaf(3.f, inter, -a1) > a2);
            }
        }

        float matchv = 0.f, fpv = 0.f;
        if (msplit == 0 && p > 0) {
            int gc = g_gt_cnt[b][p];
            if (gc > 0) {
                int off = g_csr_off[b][p];
                float bn = 0.f, bd = 1.f;
                for (int k = 0; k < gc; k++) {
                    int pos = g_csr[b][off + k];
                    float4 g = s_gb[pos];
                    float a2 = s_a2[pos];            // own track => finite
                    float lx = fmaxf(px1, g.x), ly = fmaxf(py1, g.y);
                    float rx = fminf(px2, g.z), ry = fminf(py2, g.w);
                    float iw = rx - lx;
                    float ihc = fmaxf(ry - ly, 0.f);
                    float interh = iw * ihc;                       // identical hi-test
                    swc -= (fmaf(3.f, interh, -a1) > a2);
                    float inter = fmaxf(iw, 0.f) * ihc;            // true inter for IoU
                    float uni = a1r + a2 - inter;
                    if (inter * bd > bn * uni) { bn = inter; bd = uni; }
                }
                matchv = 1.f - __fdividef(bn, bd);
            } else {
                fpv = 1.f;
            }
        }

        // warp reduce -> smem combine -> 3 atomics per block
        #pragma unroll
        for (int o = 16; o > 0; o >>= 1) {
            matchv += __shfl_down_sync(0xffffffffu, matchv, o);
            fpv    += __shfl_down_sync(0xffffffffu, fpv, o);
            swc    += __shfl_down_sync(0xffffffffu, swc, o);
        }
        if (lane == 0) {
            atomicAdd(&sm_m, matchv);
            atomicAdd(&sm_f, fpv);
            atomicAdd(&sm_s, swc);
        }
        __syncthreads();
        if (tid == 0) {
            atomicAdd(&g_match[b], sm_m);
            atomicAdd(&g_fp[b], sm_f);
            atomicAdd(&g_sw[b], sm_s);
        }
    } else {
        // ================= TEMPORAL BLOCK =================
        const float4* pb4 = pboxes + b * NN;
        const int tw = (bx - K3_SWEEP) * 8 + wid;    // 0..39
        float tsum = 0.f;
        #pragma unroll
        for (int k = 0; k < 7; k++) {
            const int t = tw * 7 + k;                // 0..279, warp-uniform
            if (t == 0 || t >= TT) continue;
            const int cnt = g_pr_cnt[b][t];
            if (cnt <= 2) continue;
            const int off = g_proff[b][t];
            if (cnt <= 32) {
                int v = (lane < cnt) ? g_tpl[b][off + lane] : 0x7fffffff;
                int rank = 0;
                for (int o = 1; o < cnt; o++) {
                    int src = lane + o;
                    if (src >= cnt) src -= cnt;
                    int ov = __shfl_sync(0xffffffffu, v, src);
                    rank += (ov < v);
                }
                if (lane < cnt) s_tsort[wid][rank] = v;
                __syncwarp();
                int myidx = (lane < cnt) ? s_tsort[wid][lane] : 0;
                float cx = 0.f, cy = 0.f;
                if (lane < cnt) {
                    float4 bxx = pb4[myidx];
                    cx = (bxx.x + bxx.z) * 0.5f;
                    cy = (bxx.y + bxx.w) * 0.5f;
                }
                float c1x = __shfl_up_sync(0xffffffffu, cx, 1);
                float c1y = __shfl_up_sync(0xffffffffu, cy, 1);
                float c0x = __shfl_up_sync(0xffffffffu, cx, 2);
                float c0y = __shfl_up_sync(0xffffffffu, cy, 2);
                float sa_l = 0.f;
                if (lane >= 2 && lane < cnt) {
                    float ax = (cx - 2.f * c1x + c0x) * SCALE_C;
                    float ay = (cy - 2.f * c1y + c0y) * SCALE_C;
                    sa_l = sqrtf(ax * ax + ay * ay);
                }
                #pragma unroll
                for (int o = 16; o > 0; o >>= 1)
                    sa_l += __shfl_down_sync(0xffffffffu, sa_l, o);
                if (lane == 0) tsum += sa_l / (float)(cnt - 2);
            } else if (lane == 0) {
                // serial fallback (data scale never hits this)
                int last = -1;
                float c0x = 0.f, c0y = 0.f, c1x = 0.f, c1y = 0.f;
                float sa = 0.f;
                for (int q = 0; q < cnt; q++) {
                    int m = 0x7fffffff;
                    for (int a = 0; a < cnt; a++) {
                        int vv = g_tpl[b][off + a];
                        if (vv > last && vv < m) m = vv;
                    }
                    last = m;
                    float4 bxx = pb4[m];
                    float cx = (bxx.x + bxx.z) * 0.5f;
                    float cy = (bxx.y + bxx.w) * 0.5f;
                    if (q >= 2) {
                        float ax = (cx - 2.f * c1x + c0x) * SCALE_C;
                        float ay = (cy - 2.f * c1y + c0y) * SCALE_C;
                        sa += sqrtf(ax * ax + ay * ay);
                    }
                    c0x = c1x; c0y = c1y; c1x = cx; c1y = cy;
                }
                tsum += sa / (float)(cnt - 2);
            }
        }
        if (lane == 0 && tsum != 0.f)
            atomicAdd(&g_traw[b], tsum);
    }

    // ---- last-block-done finalize ----
    __syncthreads();
    if (tid == 0) {
        __threadfence();
        int prev = atomicAdd(&g_done, 1);
        s_last = (prev == K3_TOTAL - 1) ? 1 : 0;
    }
    __syncthreads();
    if (s_last && tid < 32) {
        __threadfence();
        float lt = 0.f, ls = 0.f, lm = 0.f, nt = 0.f;
        if (tid < BB) {
            int bb = tid;
            int nv = g_nvalid[bb];
            int nu = g_nuni[bb];
            float has = (nv > 0) ? 1.f : 0.f;
            float mt  = *((volatile float*)&g_match[bb]);
            float fpb = *((volatile float*)&g_fp[bb]);
            int   sw  = *((volatile int*)&g_sw[bb]);
            float trw = *((volatile float*)&g_traw[bb]);
            float tr = B_FN * g_fn[bb] + mt + G_SW * (float)sw + B_FP * fpb;
            float tmp = (nv > 2) ? trw / fmaxf((float)nu, 1.f) : 0.f;
            lt = tr * has;
            ls = g_spatial[bb] * has;
            lm = tmp * has;
            nt = (float)nu * has;
        }
        #pragma unroll
        for (int o = 16; o > 0; o >>= 1) {
            lt += __shfl_down_sync(0xffffffffu, lt, o);
            ls += __shfl_down_sync(0xffffffffu, ls, o);
            lm += __shfl_down_sync(0xffffffffu, lm, o);
            nt += __shfl_down_sync(0xffffffffu, nt, o);
        }
        if (tid == 0) {
            float norm = (nt > 0.f) ? nt : 1.f;
            lt /= norm; ls /= norm; lm /= norm;
            out[0] = A_TRK * lt + A_SPA * ls + A_TMP * lm;
            out[1] = lt;
            out[2] = ls;
            out[3] = lm;
        }
    }
}

// ======================= launch =======================
extern "C" void kernel_launch(void* const* d_in, const int* in_sizes, int n_in,
                              void* d_out, int out_size)
{
    const float4* pb  = (const float4*)d_in[0];  // pred_boxes [16,2048,4] f32
    const float4* gb  = (const float4*)d_in[1];  // gt_boxes   [16,1024,4] f32
    const int*    pid = (const int*)d_in[2];     // pred_track_ids [16,2048] i32
    const int*    gid = (const int*)d_in[3];     // gt_track_ids   [16,1024] i32
    float* out = (float*)d_out;

    k1_prep<<<BB, 1024>>>(pb, gb, pid, gid);
    k3_main<<<dim3(K3_BX, BB), 256>>>(pb, out);
}

// round 15
// speedup vs baseline: 1.4936x; 1.0288x over previous
#include <cuda_runtime.h>
#include <cstdint>

#define BB 16
#define NN 2048
#define MM 1024
#define TT 256

#define SCALE_C (4.5392368437151541e-04f)  // 1/sqrt(1920^2+1080^2)
#define A_TRK 2.0f
#define A_SPA 1.5f
#define A_TMP 1.8f
#define B_FP 0.9f
#define B_FN 0.9f
#define G_SW 1.5f

#define NCX 16
#define NCELL 256
#define CELL_SCALE 0.016f       // 1/62.5
#define CMAX 15
#define F_INF __int_as_float(0x7f800000)

#define K3_SWEEP 32              // sweep blocks per batch (64 preds each)
#define K3_TEMP  5               // temporal blocks per batch
#define K3_BX (K3_SWEEP + K3_TEMP)          // 37
#define K3_TOTAL (K3_BX * BB)               // 592 = 4 * 148

// ---------------- device scratch (no allocations allowed) ----------------
__device__ int    g_gt_cnt[BB][TT];
__device__ int    g_pr_cnt[BB][TT];
__device__ int    g_csr_off[BB][TT];    // exclusive prefix of gt_cnt (track CSR)
__device__ int    g_csr[BB][MM];        // SORTED gt positions grouped by track id
__device__ float4 g_sgb[BB][MM];        // cell-sorted gt boxes
__device__ float  g_sa2[BB][MM];        // cell-sorted a2 (or +INF if track has no preds)
__device__ int    g_goff[BB][NCELL + 1];// gt cell CSR offsets
__device__ float4 g_spb[BB][NN];        // cell-sorted pred boxes
__device__ int    g_spid[BB][NN];       // cell-sorted pred ids
__device__ int    g_proff[BB][TT];      // pred-track CSR offsets
__device__ int    g_tpl[BB][NN];        // pred indices grouped by track (unordered)
__device__ float  g_fn[BB];
__device__ int    g_nuni[BB];
__device__ int    g_nvalid[BB];
__device__ float  g_match[BB];
__device__ float  g_fp[BB];
__device__ int    g_sw[BB];
__device__ float  g_spatial[BB];
__device__ float  g_traw[BB];
__device__ int    g_done;

// ======================= K1: hists + spatial + CSR builds =======================
__global__ __launch_bounds__(1024) void k1_prep(
    const float4* __restrict__ pboxes,
    const float4* __restrict__ gboxes,
    const int*    __restrict__ pid,
    const int*    __restrict__ gid)
{
    const int b = blockIdx.x;
    const int tid = threadIdx.x;
    const int lane = tid & 31, w = tid >> 5;

    __shared__ int   s_gt[TT], s_pr[TT];
    __shared__ float s_mw[TT], s_mh[TT], s_dw[TT], s_dh[TT];
    __shared__ int   s_toff[TT], s_tcur[TT];
    __shared__ int   s_proff[TT], s_prcur[TT];
    __shared__ float s_w[NN], s_h[NN];
    __shared__ int   s_p[NN];              // packed: pid | (cell<<8)
    __shared__ float s_ga2[MM];
    __shared__ int   s_gcnt[NCELL], s_goffs[NCELL], s_gcur[NCELL];
    __shared__ int   s_pcnt[NCELL], s_poffs[NCELL], s_pcur[NCELL];
    __shared__ int   s_ws[4][8];
    __shared__ float r_f[32], r_s[32];
    __shared__ int   r_u[32], r_v[32];

    if (tid < TT) {
        s_gt[tid] = 0; s_pr[tid] = 0;
        s_mw[tid] = 0.f; s_mh[tid] = 0.f;
        s_dw[tid] = 0.f; s_dh[tid] = 0.f;
    }
    if (tid < NCELL) {
        s_gcnt[tid] = 0; s_gcur[tid] = 0;
        s_pcnt[tid] = 0; s_pcur[tid] = 0;
    }
    if (b == 0 && tid == 0) g_done = 0;
    if (tid == 0) { g_match[b] = 0.f; g_fp[b] = 0.f; g_sw[b] = 0; g_traw[b] = 0.f; }
    __syncthreads();

    // ---- phase 1: histograms + stashes ----
    const int* gidb = gid + b * MM;
    const float4* gb4 = gboxes + b * MM;
    if (tid < MM) {
        float4 g = gb4[tid];
        int t = gidb[tid];
        float a2 = fmaxf(g.z - g.x, 0.f) * fmaxf(g.w - g.y, 0.f);
        int cx = min((int)(g.x * CELL_SCALE), CMAX);
        int cy = min((int)(g.y * CELL_SCALE), CMAX);
        int c = cy * NCX + cx;
        s_ga2[tid] = a2;
        atomicAdd(&s_gt[t], 1);
        atomicAdd(&s_gcnt[c], 1);
    }
    const int* pidb = pid + b * NN;
    const float4* pb4 = pboxes + b * NN;
    int nvalid = 0;
    #pragma unroll
    for (int k = 0; k < 2; k++) {
        int i = tid + k * 1024;
        int p = pidb[i];
        float4 bx = pb4[i];
        float bw = bx.z - bx.x, bh = bx.w - bx.y;
        int cx = min((int)(bx.x * CELL_SCALE), CMAX);
        int cy = min((int)(bx.y * CELL_SCALE), CMAX);
        int c = cy * NCX + cx;
        s_w[i] = bw; s_h[i] = bh;
        s_p[i] = p | (c << 8);             // pid in [0,255], cell in [0,255]
        atomicAdd(&s_pcnt[c], 1);
        if (p > 0) {
            atomicAdd(&s_pr[p], 1);
            atomicAdd(&s_mw[p], bw);
            atomicAdd(&s_mh[p], bh);
            nvalid++;
        }
    }
    __syncthreads();

    // ---- phase 2a: means + publish counts ----
    if (tid < TT) {
        int c = s_pr[tid];
        float cs = fmaxf((float)c, 1.f);
        s_mw[tid] = s_mw[tid] / cs;
        s_mh[tid] = s_mh[tid] / cs;
        g_pr_cnt[b][tid] = c;
        g_gt_cnt[b][tid] = s_gt[tid];
    }

    // ---- phase 2b: four parallel 256-bin exclusive scans ----
    // seg 0: track gt_cnt -> s_toff/g_csr_off ; seg 1: gt cells -> s_goffs/g_goff
    // seg 2: pred cells -> s_poffs           ; seg 3: pred-track -> s_proff/g_proff
    {
        const int seg = tid >> 8;
        const int c = tid & 255;
        const int w8 = (tid >> 5) & 7;
        int val = (seg == 0) ? s_gt[c] : (seg == 1) ? s_gcnt[c]
                : (seg == 2) ? s_pcnt[c] : s_pr[c];
        int incl = val;
        #pragma unroll
        for (int o = 1; o < 32; o <<= 1) {
            int n = __shfl_up_sync(0xffffffffu, incl, o);
            if (lane >= o) incl += n;
        }
        if (lane == 31) s_ws[seg][w8] = incl;
        __syncthreads();
        int woff = 0;
        #pragma unroll
        for (int k = 0; k < 8; k++) if (k < w8) woff += s_ws[seg][k];
        int excl = woff + incl - val;
        if (seg == 0)      { s_toff[c] = excl; s_tcur[c] = 0; g_csr_off[b][c] = excl; }
        else if (seg == 1) { s_goffs[c] = excl; g_goff[b][c] = excl;
                             if (c == 0) g_goff[b][NCELL] = MM; }
        else if (seg == 2) { s_poffs[c] = excl; }
        else               { s_proff[c] = excl; s_prcur[c] = 0; g_proff[b][c] = excl; }
    }
    __syncthreads();

    // ---- phase 3: deviations + all scatters ----
    #pragma unroll
    for (int k = 0; k < 2; k++) {
        int i = tid + k * 1024;
        int pk = s_p[i];
        int p = pk & 0xFF;
        int c = pk >> 8;
        float4 bx = pb4[i];                // L1-resident reload
        if (p > 0) {
            atomicAdd(&s_dw[p], fabsf(s_w[i] - s_mw[p]));
            atomicAdd(&s_dh[p], fabsf(s_h[i] - s_mh[p]));
            int tp = s_proff[p] + atomicAdd(&s_prcur[p], 1);
            g_tpl[b][tp] = i;
        }
        int pos = s_poffs[c] + atomicAdd(&s_pcur[c], 1);
        g_spb[b][pos] = bx;
        g_spid[b][pos] = p;
    }
    if (tid < MM) {
        int j = tid;
        float4 g = gb4[j];                 // L1-resident reload
        int t = gidb[j];
        int cx = min((int)(g.x * CELL_SCALE), CMAX);
        int cy = min((int)(g.y * CELL_SCALE), CMAX);
        int c = cy * NCX + cx;
        int pos = s_goffs[c] + atomicAdd(&s_gcur[c], 1);
        g_sgb[b][pos] = g;
        g_sa2[b][pos] = (s_pr[t] > 0) ? s_ga2[j] : F_INF;
        int tp = s_toff[t] + atomicAdd(&s_tcur[t], 1);
        g_csr[b][tp] = pos;                          // sorted position
    }
    __syncthreads();

    // ---- phase 4: per-track terms + block reduce ----
    float fn = 0.f, sp = 0.f;
    int nu = 0;
    if (tid < TT) {
        int c  = s_pr[tid];
        int gc = s_gt[tid];
        fn = (gc > 0 && c == 0) ? (float)gc : 0.f;
        nu = (c > 0) ? 1 : 0;
        sp = (c > 1) ? (s_dw[tid] + s_dh[tid]) * SCALE_C / (float)c : 0.f;
    }
    #pragma unroll
    for (int o = 16; o > 0; o >>= 1) {
        fn     += __shfl_down_sync(0xffffffffu, fn, o);
        sp     += __shfl_down_sync(0xffffffffu, sp, o);
        nu     += __shfl_down_sync(0xffffffffu, nu, o);
        nvalid += __shfl_down_sync(0xffffffffu, nvalid, o);
    }
    if (lane == 0) { r_f[w] = fn; r_s[w] = sp; r_u[w] = nu; r_v[w] = nvalid; }
    __syncthreads();
    if (tid == 0) {
        float F = 0.f, S = 0.f; int U = 0, V = 0;
        #pragma unroll
        for (int k = 0; k < 32; k++) { F += r_f[k]; S += r_s[k]; U += r_u[k]; V += r_v[k]; }
        g_fn[b] = F; g_nuni[b] = U; g_nvalid[b] = V;
        g_spatial[b] = (V > 1) ? S / fmaxf((float)U, 1.f) : 0.f;
    }
}

// ======================= K3: sweep blocks + temporal blocks + finalize =======================
// grid (37, BB), 256 threads. bx<32: 64 preds/block, 4-way msplit sweep.
// bx>=32: temporal, 8 warps x 7 tracks each (40 warps cover 256 tracks).
__global__ __launch_bounds__(256) void k3_main(
    const float4* __restrict__ pboxes,
    float* __restrict__ out)
{
    const int b = blockIdx.y;
    const int bx = blockIdx.x;
    const int tid = threadIdx.x;
    const int lane = tid & 31;
    const int wid = tid >> 5;

    __shared__ __align__(16) float4 s_gb[MM];   // sorted gt boxes  16 KB
    __shared__ __align__(16) float  s_a2[MM];   // sorted a2/INF     4 KB
    __shared__ int   s_goff[NCELL + 1];         // 1 KB
    __shared__ float sm_m, sm_f;
    __shared__ int   sm_s;
    __shared__ int   s_tsort[8][33];
    __shared__ int   s_last;

    if (bx < K3_SWEEP) {
        // ================= SWEEP BLOCK =================
        const float4* __restrict__ sgbg = g_sgb[b];
        const float*  __restrict__ sa2g = g_sa2[b];
        #pragma unroll
        for (int k = 0; k < 4; k++) {
            int j = tid + k * 256;
            s_gb[j] = sgbg[j];
            s_a2[j] = sa2g[j];
        }
        s_goff[tid] = g_goff[b][tid];
        if (tid == 0) {
            s_goff[NCELL] = g_goff[b][NCELL];
            sm_m = 0.f; sm_f = 0.f; sm_s = 0;
        }
        __syncthreads();

        const int pred_l = tid & 63;
        const int msplit = tid >> 6;                 // warp-uniform (wid>>1)
        const int slot = bx * 64 + pred_l;
        const int p = g_spid[b][slot];               // coalesced
        const float4 pbx = g_spb[b][slot];           // coalesced
        const float px1 = pbx.x, py1 = pbx.y, px2 = pbx.z, py2 = pbx.w;
        const float a1r = fmaxf(px2 - px1, 0.f) * fmaxf(py2 - py1, 0.f);
        const float a1 = (p > 0) ? a1r : F_INF;      // INF => hi-test always false

        // window cells (conservative: gt corner in [px1-102, px2] x [py1-102, py2])
        int cx0 = (int)(fmaxf(px1 - 103.f, 0.f) * CELL_SCALE);
        int cx1 = min((int)((px2 + 1.f) * CELL_SCALE), CMAX);
        int cy0 = (int)(fmaxf(py1 - 103.f, 0.f) * CELL_SCALE);
        int cy1 = min((int)((py2 + 1.f) * CELL_SCALE), CMAX);
        #pragma unroll
        for (int o = 16; o > 0; o >>= 1) {
            cx0 = min(cx0, __shfl_xor_sync(0xffffffffu, cx0, o));
            cx1 = max(cx1, __shfl_xor_sync(0xffffffffu, cx1, o));
            cy0 = min(cy0, __shfl_xor_sync(0xffffffffu, cy0, o));
            cy1 = max(cy1, __shfl_xor_sync(0xffffffffu, cy1, o));
        }

        int swc = 0;
        for (int cy = cy0; cy <= cy1; cy++) {
            const int rowb = cy * NCX;
            const int jlo = s_goff[rowb + cx0];
            const int jhi = s_goff[rowb + cx1 + 1];
            #pragma unroll 4
            for (int j = jlo + msplit; j < jhi; j += 4) {     // warp-uniform broadcast
                float4 g = s_gb[j];
                float a2 = s_a2[j];
                float lx = fmaxf(px1, g.x), ly = fmaxf(py1, g.y);
                float rx = fminf(px2, g.z), ry = fminf(py2, g.w);
                float inter = (rx - lx) * fmaxf(ry - ly, 0.f);   // single-clamp
                swc += (fmaf(3.f, inter, -a1) > a2);
            }
        }

        float matchv = 0.f, fpv = 0.f;
        if (msplit == 0 && p > 0) {
            int gc = g_gt_cnt[b][p];
            if (gc > 0) {
                int off = g_csr_off[b][p];
                float bn = 0.f, bd = 1.f;
                for (int k = 0; k < gc; k++) {
                    int pos = g_csr[b][off + k];
                    float4 g = s_gb[pos];
                    float a2 = s_a2[pos];            // own track => finite
                    float lx = fmaxf(px1, g.x), ly = fmaxf(py1, g.y);
                    float rx = fminf(px2, g.z), ry = fminf(py2, g.w);
                    float iw = rx - lx;
                    float ihc = fmaxf(ry - ly, 0.f);
                    float interh = iw * ihc;                       // identical hi-test
                    swc -= (fmaf(3.f, interh, -a1) > a2);
                    float inter = fmaxf(iw, 0.f) * ihc;            // true inter for IoU
                    float uni = a1r + a2 - inter;
                    if (inter * bd > bn * uni) { bn = inter; bd = uni; }
                }
                matchv = 1.f - __fdividef(bn, bd);
            } else {
                fpv = 1.f;
            }
        }

        // warp reduce -> smem combine -> 3 atomics per block
        #pragma unroll
        for (int o = 16; o > 0; o >>= 1) {
            matchv += __shfl_down_sync(0xffffffffu, matchv, o);
            fpv    += __shfl_down_sync(0xffffffffu, fpv, o);
            swc    += __shfl_down_sync(0xffffffffu, swc, o);
        }
        if (lane == 0) {
            atomicAdd(&sm_m, matchv);
            atomicAdd(&sm_f, fpv);
            atomicAdd(&sm_s, swc);
        }
        __syncthreads();
        if (tid == 0) {
            atomicAdd(&g_match[b], sm_m);
            atomicAdd(&g_fp[b], sm_f);
            atomicAdd(&g_sw[b], sm_s);
        }
    } else {
        // ================= TEMPORAL BLOCK =================
        const float4* pb4 = pboxes + b * NN;
        const int tw = (bx - K3_SWEEP) * 8 + wid;    // 0..39
        float tsum = 0.f;
        #pragma unroll
        for (int k = 0; k < 7; k++) {
            const int t = tw * 7 + k;                // 0..279, warp-uniform
            if (t == 0 || t >= TT) continue;
            const int cnt = g_pr_cnt[b][t];
            if (cnt <= 2) continue;
            const int off = g_proff[b][t];
            if (cnt <= 32) {
                int v = (lane < cnt) ? g_tpl[b][off + lane] : 0x7fffffff;
                int rank = 0;
                for (int o = 1; o < cnt; o++) {
                    int src = lane + o;
                    if (src >= cnt) src -= cnt;
                    int ov = __shfl_sync(0xffffffffu, v, src);
                    rank += (ov < v);
                }
                if (lane < cnt) s_tsort[wid][rank] = v;
                __syncwarp();
                int myidx = (lane < cnt) ? s_tsort[wid][lane] : 0;
                float cx = 0.f, cy = 0.f;
                if (lane < cnt) {
                    float4 bxx = pb4[myidx];
                    cx = (bxx.x + bxx.z) * 0.5f;
                    cy = (bxx.y + bxx.w) * 0.5f;
                }
                float c1x = __shfl_up_sync(0xffffffffu, cx, 1);
                float c1y = __shfl_up_sync(0xffffffffu, cy, 1);
                float c0x = __shfl_up_sync(0xffffffffu, cx, 2);
                float c0y = __shfl_up_sync(0xffffffffu, cy, 2);
                float sa_l = 0.f;
                if (lane >= 2 && lane < cnt) {
                    float ax = (cx - 2.f * c1x + c0x) * SCALE_C;
                    float ay = (cy - 2.f * c1y + c0y) * SCALE_C;
                    sa_l = sqrtf(ax * ax + ay * ay);
                }
                #pragma unroll
                for (int o = 16; o > 0; o >>= 1)
                    sa_l += __shfl_down_sync(0xffffffffu, sa_l, o);
                if (lane == 0) tsum += sa_l / (float)(cnt - 2);
            } else if (lane == 0) {
                // serial fallback (data scale never hits this)
                int last = -1;
                float c0x = 0.f, c0y = 0.f, c1x = 0.f, c1y = 0.f;
                float sa = 0.f;
                for (int q = 0; q < cnt; q++) {
                    int m = 0x7fffffff;
                    for (int a = 0; a < cnt; a++) {
                        int vv = g_tpl[b][off + a];
                        if (vv > last && vv < m) m = vv;
                    }
                    last = m;
                    float4 bxx = pb4[m];
                    float cx = (bxx.x + bxx.z) * 0.5f;
                    float cy = (bxx.y + bxx.w) * 0.5f;
                    if (q >= 2) {
                        float ax = (cx - 2.f * c1x + c0x) * SCALE_C;
                        float ay = (cy - 2.f * c1y + c0y) * SCALE_C;
                        sa += sqrtf(ax * ax + ay * ay);
                    }
                    c0x = c1x; c0y = c1y; c1x = cx; c1y = cy;
                }
                tsum += sa / (float)(cnt - 2);
            }
        }
        if (lane == 0 && tsum != 0.f)
            atomicAdd(&g_traw[b], tsum);
    }

    // ---- last-block-done finalize ----
    __syncthreads();
    if (tid == 0) {
        __threadfence();
        int prev = atomicAdd(&g_done, 1);
        s_last = (prev == K3_TOTAL - 1) ? 1 : 0;
    }
    __syncthreads();
    if (s_last && tid < 32) {
        __threadfence();
        float lt = 0.f, ls = 0.f, lm = 0.f, nt = 0.f;
        if (tid < BB) {
            int bb = tid;
            int nv = g_nvalid[bb];
            int nu = g_nuni[bb];
            float has = (nv > 0) ? 1.f : 0.f;
            float mt  = *((volatile float*)&g_match[bb]);
            float fpb = *((volatile float*)&g_fp[bb]);
            int   sw  = *((volatile int*)&g_sw[bb]);
            float trw = *((volatile float*)&g_traw[bb]);
            float tr = B_FN * g_fn[bb] + mt + G_SW * (float)sw + B_FP * fpb;
            float tmp = (nv > 2) ? trw / fmaxf((float)nu, 1.f) : 0.f;
            lt = tr * has;
            ls = g_spatial[bb] * has;
            lm = tmp * has;
            nt = (float)nu * has;
        }
        #pragma unroll
        for (int o = 16; o > 0; o >>= 1) {
            lt += __shfl_down_sync(0xffffffffu, lt, o);
            ls += __shfl_down_sync(0xffffffffu, ls, o);
            lm += __shfl_down_sync(0xffffffffu, lm, o);
            nt += __shfl_down_sync(0xffffffffu, nt, o);
        }
        if (tid == 0) {
            float norm = (nt > 0.f) ? nt : 1.f;
            lt /= norm; ls /= norm; lm /= norm;
            out[0] = A_TRK * lt + A_SPA * ls + A_TMP * lm;
            out[1] = lt;
            out[2] = ls;
            out[3] = lm;
        }
    }
}

// ======================= launch =======================
extern "C" void kernel_launch(void* const* d_in, const int* in_sizes, int n_in,
                              void* d_out, int out_size)
{
    const float4* pb  = (const float4*)d_in[0];  // pred_boxes [16,2048,4] f32
    const float4* gb  = (const float4*)d_in[1];  // gt_boxes   [16,1024,4] f32
    const int*    pid = (const int*)d_in[2];     // pred_track_ids [16,2048] i32
    const int*    gid = (const int*)d_in[3];     // gt_track_ids   [16,1024] i32
    float* out = (float*)d_out;

    k1_prep<<<BB, 1024>>>(pb, gb, pid, gid);
    k3_main<<<dim3(K3_BX, BB), 256>>>(pb, out);
}

// round 16
// speedup vs baseline: 1.5636x; 1.0469x over previous
#include <cuda_runtime.h>
#include <cstdint>

#define BB 16
#define NN 2048
#define MM 1024
#define TT 256

#define SCALE_C (4.5392368437151541e-04f)  // 1/sqrt(1920^2+1080^2)
#define A_TRK 2.0f
#define A_SPA 1.5f
#define A_TMP 1.8f
#define B_FP 0.9f
#define B_FN 0.9f
#define G_SW 1.5f

#define NCX 16
#define NCELL 256
#define CELL_SCALE 0.016f       // 1/62.5
#define CMAX 15
#define F_INF __int_as_float(0x7f800000)

#define K3_SWEEP 32              // sweep blocks per batch (64 preds each)
#define K3_TEMP  5               // temporal blocks per batch
#define K3_BX (K3_SWEEP + K3_TEMP)          // 37
#define K3_TOTAL (K3_BX * BB)               // 592 = 4 * 148

// ---------------- device scratch (no allocations allowed) ----------------
__device__ int    g_gt_cnt[BB][TT];
__device__ int    g_pr_cnt[BB][TT];
__device__ int    g_csr_off[BB][TT];    // exclusive prefix of gt_cnt (track CSR)
__device__ int    g_csr[BB][MM];        // SORTED gt positions grouped by track id
__device__ float4 g_sgb[BB][MM];        // cell-sorted gt boxes
__device__ float  g_sa2[BB][MM];        // cell-sorted a2 (or +INF if track has no preds)
__device__ int    g_goff[BB][NCELL + 1];// gt cell CSR offsets
__device__ float4 g_spb[BB][NN];        // cell-sorted pred boxes
__device__ int    g_spid[BB][NN];       // cell-sorted pred ids
__device__ int    g_proff[BB][TT];      // pred-track CSR offsets
__device__ int    g_tpl[BB][NN];        // pred indices grouped by track (unordered)
__device__ float  g_fn[BB];
__device__ int    g_nuni[BB];
__device__ int    g_nvalid[BB];
__device__ float  g_match[BB];
__device__ float  g_fp[BB];
__device__ int    g_sw[BB];
__device__ float  g_spatial[BB];
__device__ float  g_traw[BB];
__device__ int    g_done;

// ======================= K1: grid (2, BB). role 0 = pred side, role 1 = gt side ==============
__global__ __launch_bounds__(1024) void k1_prep(
    const float4* __restrict__ pboxes,
    const float4* __restrict__ gboxes,
    const int*    __restrict__ pid,
    const int*    __restrict__ gid)
{
    const int role = blockIdx.x;
    const int b = blockIdx.y;
    const int tid = threadIdx.x;
    const int lane = tid & 31, w = tid >> 5;

    const int* pidb = pid + b * NN;

    if (role == 0) {
        // ================== PRED BLOCK ==================
        __shared__ int   s_pr[TT];
        __shared__ float s_mw[TT], s_mh[TT], s_dw[TT], s_dh[TT];
        __shared__ int   s_proff[TT], s_prcur[TT];
        __shared__ int   s_pcnt[NCELL], s_poffs[NCELL], s_pcur[NCELL];
        __shared__ int   s_p[NN];            // packed: pid | (cell<<8)
        __shared__ int   s_ws[2][8];
        __shared__ float r_s[32];
        __shared__ int   r_u[32], r_v[32];

        if (tid < TT) {
            s_pr[tid] = 0;
            s_mw[tid] = 0.f; s_mh[tid] = 0.f;
            s_dw[tid] = 0.f; s_dh[tid] = 0.f;
            s_pcnt[tid] = 0; s_pcur[tid] = 0;
        }
        if (b == 0 && tid == 0) g_done = 0;
        if (tid == 0) { g_match[b] = 0.f; g_fp[b] = 0.f; g_sw[b] = 0; g_traw[b] = 0.f; }
        __syncthreads();

        const float4* pb4 = pboxes + b * NN;
        int nvalid = 0;
        #pragma unroll
        for (int k = 0; k < 2; k++) {
            int i = tid + k * 1024;
            int p = pidb[i];
            float4 bx = pb4[i];
            int cx = min((int)(bx.x * CELL_SCALE), CMAX);
            int cy = min((int)(bx.y * CELL_SCALE), CMAX);
            int c = cy * NCX + cx;
            s_p[i] = p | (c << 8);
            atomicAdd(&s_pcnt[c], 1);
            if (p > 0) {
                atomicAdd(&s_pr[p], 1);
                atomicAdd(&s_mw[p], bx.z - bx.x);
                atomicAdd(&s_mh[p], bx.w - bx.y);
                nvalid++;
            }
        }
        __syncthreads();

        // means + publish counts
        if (tid < TT) {
            int c = s_pr[tid];
            float cs = fmaxf((float)c, 1.f);
            s_mw[tid] = s_mw[tid] / cs;
            s_mh[tid] = s_mh[tid] / cs;
            g_pr_cnt[b][tid] = c;
        }
        // two parallel 256-bin scans: seg 0 = pred cells, seg 1 = pred-track
        {
            const int seg = tid >> 8;            // 0..3
            const int c = tid & 255;
            const int w8 = (tid >> 5) & 7;
            int val = 0;
            if (seg == 0) val = s_pcnt[c];
            else if (seg == 1) val = s_pr[c];
            int incl = val;
            #pragma unroll
            for (int o = 1; o < 32; o <<= 1) {
                int n = __shfl_up_sync(0xffffffffu, incl, o);
                if (lane >= o) incl += n;
            }
            if (seg < 2 && lane == 31) s_ws[seg][w8] = incl;
            __syncthreads();
            if (seg < 2) {
                int woff = 0;
                #pragma unroll
                for (int k = 0; k < 8; k++) if (k < w8) woff += s_ws[seg][k];
                int excl = woff + incl - val;
                if (seg == 0) { s_poffs[c] = excl; }
                else          { s_proff[c] = excl; s_prcur[c] = 0; g_proff[b][c] = excl; }
            }
        }
        __syncthreads();

        // deviations + scatters
        #pragma unroll
        for (int k = 0; k < 2; k++) {
            int i = tid + k * 1024;
            int pk = s_p[i];
            int p = pk & 0xFF;
            int c = pk >> 8;
            float4 bx = pb4[i];                // L1-resident reload
            if (p > 0) {
                atomicAdd(&s_dw[p], fabsf((bx.z - bx.x) - s_mw[p]));
                atomicAdd(&s_dh[p], fabsf((bx.w - bx.y) - s_mh[p]));
                int tp = s_proff[p] + atomicAdd(&s_prcur[p], 1);
                g_tpl[b][tp] = i;
            }
            int pos = s_poffs[c] + atomicAdd(&s_pcur[c], 1);
            g_spb[b][pos] = bx;
            g_spid[b][pos] = p;
        }
        __syncthreads();

        // spatial / nuni / nvalid reduce
        float sp = 0.f;
        int nu = 0;
        if (tid < TT) {
            int c = s_pr[tid];
            nu = (c > 0) ? 1 : 0;
            sp = (c > 1) ? (s_dw[tid] + s_dh[tid]) * SCALE_C / (float)c : 0.f;
        }
        #pragma unroll
        for (int o = 16; o > 0; o >>= 1) {
            sp     += __shfl_down_sync(0xffffffffu, sp, o);
            nu     += __shfl_down_sync(0xffffffffu, nu, o);
            nvalid += __shfl_down_sync(0xffffffffu, nvalid, o);
        }
        if (lane == 0) { r_s[w] = sp; r_u[w] = nu; r_v[w] = nvalid; }
        __syncthreads();
        if (tid == 0) {
            float S = 0.f; int U = 0, V = 0;
            #pragma unroll
            for (int k = 0; k < 32; k++) { S += r_s[k]; U += r_u[k]; V += r_v[k]; }
            g_nuni[b] = U; g_nvalid[b] = V;
            g_spatial[b] = (V > 1) ? S / fmaxf((float)U, 1.f) : 0.f;
        }
    } else {
        // ================== GT BLOCK ==================
        __shared__ int   s_gt[TT], s_pr[TT];
        __shared__ int   s_toff[TT], s_tcur[TT];
        __shared__ int   s_gcnt[NCELL], s_goffs[NCELL], s_gcur[NCELL];
        __shared__ float s_ga2[MM];
        __shared__ int   s_ws[2][8];
        __shared__ float r_f[32];

        if (tid < TT) {
            s_gt[tid] = 0; s_pr[tid] = 0;
            s_gcnt[tid] = 0; s_gcur[tid] = 0;
        }
        __syncthreads();

        const int* gidb = gid + b * MM;
        const float4* gb4 = gboxes + b * MM;
        if (tid < MM) {
            float4 g = gb4[tid];
            int t = gidb[tid];
            float a2 = fmaxf(g.z - g.x, 0.f) * fmaxf(g.w - g.y, 0.f);
            int cx = min((int)(g.x * CELL_SCALE), CMAX);
            int cy = min((int)(g.y * CELL_SCALE), CMAX);
            s_ga2[tid] = a2;
            atomicAdd(&s_gt[t], 1);
            atomicAdd(&s_gcnt[cy * NCX + cx], 1);
        }
        // rebuild pred-track counts (needed for a2/INF flag and fn)
        #pragma unroll
        for (int k = 0; k < 2; k++) {
            int p = pidb[tid + k * 1024];
            if (p > 0) atomicAdd(&s_pr[p], 1);
        }
        __syncthreads();

        if (tid < TT) g_gt_cnt[b][tid] = s_gt[tid];
        // two parallel scans: seg 0 = gt track (CSR), seg 1 = gt cells
        {
            const int seg = tid >> 8;
            const int c = tid & 255;
            const int w8 = (tid >> 5) & 7;
            int val = 0;
            if (seg == 0) val = s_gt[c];
            else if (seg == 1) val = s_gcnt[c];
            int incl = val;
            #pragma unroll
            for (int o = 1; o < 32; o <<= 1) {
                int n = __shfl_up_sync(0xffffffffu, incl, o);
                if (lane >= o) incl += n;
            }
            if (seg < 2 && lane == 31) s_ws[seg][w8] = incl;
            __syncthreads();
            if (seg < 2) {
                int woff = 0;
                #pragma unroll
                for (int k = 0; k < 8; k++) if (k < w8) woff += s_ws[seg][k];
                int excl = woff + incl - val;
                if (seg == 0) { s_toff[c] = excl; s_tcur[c] = 0; g_csr_off[b][c] = excl; }
                else          { s_goffs[c] = excl; g_goff[b][c] = excl;
                                if (c == 0) g_goff[b][NCELL] = MM; }
            }
        }
        __syncthreads();

        // gt scatter + CSR
        if (tid < MM) {
            int j = tid;
            float4 g = gb4[j];                 // L1-resident reload
            int t = gidb[j];
            int cx = min((int)(g.x * CELL_SCALE), CMAX);
            int cy = min((int)(g.y * CELL_SCALE), CMAX);
            int c = cy * NCX + cx;
            int pos = s_goffs[c] + atomicAdd(&s_gcur[c], 1);
            g_sgb[b][pos] = g;
            g_sa2[b][pos] = (s_pr[t] > 0) ? s_ga2[j] : F_INF;
            int tp = s_toff[t] + atomicAdd(&s_tcur[t], 1);
            g_csr[b][tp] = pos;
        }
        __syncthreads();

        // fn reduce
        float fn = 0.f;
        if (tid < TT) {
            int gc = s_gt[tid];
            fn = (gc > 0 && s_pr[tid] == 0) ? (float)gc : 0.f;
        }
        #pragma unroll
        for (int o = 16; o > 0; o >>= 1)
            fn += __shfl_down_sync(0xffffffffu, fn, o);
        if (lane == 0) r_f[w] = fn;
        __syncthreads();
        if (tid == 0) {
            float F = 0.f;
            #pragma unroll
            for (int k = 0; k < 32; k++) F += r_f[k];
            g_fn[b] = F;
        }
    }
}

// ======================= K3: sweep blocks + temporal blocks + finalize =======================
// grid (37, BB), 256 threads. bx<32: 64 preds/block, 4-way msplit sweep.
// bx>=32: temporal, 8 warps x 7 tracks each (40 warps cover 256 tracks).
__global__ __launch_bounds__(256) void k3_main(
    const float4* __restrict__ pboxes,
    float* __restrict__ out)
{
    const int b = blockIdx.y;
    const int bx = blockIdx.x;
    const int tid = threadIdx.x;
    const int lane = tid & 31;
    const int wid = tid >> 5;

    __shared__ __align__(16) float4 s_gb[MM];   // sorted gt boxes  16 KB
    __shared__ __align__(16) float  s_a2[MM];   // sorted a2/INF     4 KB
    __shared__ int   s_goff[NCELL + 1];         // 1 KB
    __shared__ float sm_m, sm_f;
    __shared__ int   sm_s;
    __shared__ int   s_tsort[8][33];
    __shared__ int   s_last;

    if (bx < K3_SWEEP) {
        // ================= SWEEP BLOCK =================
        const float4* __restrict__ sgbg = g_sgb[b];
        const float*  __restrict__ sa2g = g_sa2[b];
        #pragma unroll
        for (int k = 0; k < 4; k++) {
            int j = tid + k * 256;
            s_gb[j] = sgbg[j];
            s_a2[j] = sa2g[j];
        }
        s_goff[tid] = g_goff[b][tid];
        if (tid == 0) {
            s_goff[NCELL] = g_goff[b][NCELL];
            sm_m = 0.f; sm_f = 0.f; sm_s = 0;
        }
        __syncthreads();

        const int pred_l = tid & 63;
        const int msplit = tid >> 6;                 // warp-uniform (wid>>1)
        const int slot = bx * 64 + pred_l;
        const int p = g_spid[b][slot];               // coalesced
        const float4 pbx = g_spb[b][slot];           // coalesced
        const float px1 = pbx.x, py1 = pbx.y, px2 = pbx.z, py2 = pbx.w;
        const float a1r = fmaxf(px2 - px1, 0.f) * fmaxf(py2 - py1, 0.f);
        const float a1 = (p > 0) ? a1r : F_INF;      // INF => hi-test always false

        // window cells (conservative: gt corner in [px1-102, px2] x [py1-102, py2])
        int cx0 = (int)(fmaxf(px1 - 103.f, 0.f) * CELL_SCALE);
        int cx1 = min((int)((px2 + 1.f) * CELL_SCALE), CMAX);
        int cy0 = (int)(fmaxf(py1 - 103.f, 0.f) * CELL_SCALE);
        int cy1 = min((int)((py2 + 1.f) * CELL_SCALE), CMAX);
        #pragma unroll
        for (int o = 16; o > 0; o >>= 1) {
            cx0 = min(cx0, __shfl_xor_sync(0xffffffffu, cx0, o));
            cx1 = max(cx1, __shfl_xor_sync(0xffffffffu, cx1, o));
            cy0 = min(cy0, __shfl_xor_sync(0xffffffffu, cy0, o));
            cy1 = max(cy1, __shfl_xor_sync(0xffffffffu, cy1, o));
        }

        int swc = 0;
        for (int cy = cy0; cy <= cy1; cy++) {
            const int rowb = cy * NCX;
            const int jlo = s_goff[rowb + cx0];
            const int jhi = s_goff[rowb + cx1 + 1];
            #pragma unroll 4
            for (int j = jlo + msplit; j < jhi; j += 4) {     // warp-uniform broadcast
                float4 g = s_gb[j];
                float a2 = s_a2[j];
                float lx = fmaxf(px1, g.x), ly = fmaxf(py1, g.y);
                float rx = fminf(px2, g.z), ry = fminf(py2, g.w);
                float inter = (rx - lx) * fmaxf(ry - ly, 0.f);   // single-clamp
                swc += (fmaf(3.f, inter, -a1) > a2);
            }
        }

        float matchv = 0.f, fpv = 0.f;
        if (msplit == 0 && p > 0) {
            int gc = g_gt_cnt[b][p];
            if (gc > 0) {
                int off = g_csr_off[b][p];
                float bn = 0.f, bd = 1.f;
                for (int k = 0; k < gc; k++) {
                    int pos = g_csr[b][off + k];
                    float4 g = s_gb[pos];
                    float a2 = s_a2[pos];            // own track => finite
                    float lx = fmaxf(px1, g.x), ly = fmaxf(py1, g.y);
                    float rx = fminf(px2, g.z), ry = fminf(py2, g.w);
                    float iw = rx - lx;
                    float ihc = fmaxf(ry - ly, 0.f);
                    float interh = iw * ihc;                       // identical hi-test
                    swc -= (fmaf(3.f, interh, -a1) > a2);
                    float inter = fmaxf(iw, 0.f) * ihc;            // true inter for IoU
                    float uni = a1r + a2 - inter;
                    if (inter * bd > bn * uni) { bn = inter; bd = uni; }
                }
                matchv = 1.f - __fdividef(bn, bd);
            } else {
                fpv = 1.f;
            }
        }

        // warp reduce -> smem combine -> 3 atomics per block
        #pragma unroll
        for (int o = 16; o > 0; o >>= 1) {
            matchv += __shfl_down_sync(0xffffffffu, matchv, o);
            fpv    += __shfl_down_sync(0xffffffffu, fpv, o);
            swc    += __shfl_down_sync(0xffffffffu, swc, o);
        }
        if (lane == 0) {
            atomicAdd(&sm_m, matchv);
            atomicAdd(&sm_f, fpv);
            atomicAdd(&sm_s, swc);
        }
        __syncthreads();
        if (tid == 0) {
            atomicAdd(&g_match[b], sm_m);
            atomicAdd(&g_fp[b], sm_f);
            atomicAdd(&g_sw[b], sm_s);
        }
    } else {
        // ================= TEMPORAL BLOCK =================
        const float4* pb4 = pboxes + b * NN;
        const int tw = (bx - K3_SWEEP) * 8 + wid;    // 0..39
        float tsum = 0.f;
        #pragma unroll
        for (int k = 0; k < 7; k++) {
            const int t = tw * 7 + k;                // 0..279, warp-uniform
            if (t == 0 || t >= TT) continue;
            const int cnt = g_pr_cnt[b][t];
            if (cnt <= 2) continue;
            const int off = g_proff[b][t];
            if (cnt <= 32) {
                int v = (lane < cnt) ? g_tpl[b][off + lane] : 0x7fffffff;
                int rank = 0;
                for (int o = 1; o < cnt; o++) {
                    int src = lane + o;
                    if (src >= cnt) src -= cnt;
                    int ov = __shfl_sync(0xffffffffu, v, src);
                    rank += (ov < v);
                }
                if (lane < cnt) s_tsort[wid][rank] = v;
                __syncwarp();
                int myidx = (lane < cnt) ? s_tsort[wid][lane] : 0;
                float cx = 0.f, cy = 0.f;
                if (lane < cnt) {
                    float4 bxx = pb4[myidx];
                    cx = (bxx.x + bxx.z) * 0.5f;
                    cy = (bxx.y + bxx.w) * 0.5f;
                }
                float c1x = __shfl_up_sync(0xffffffffu, cx, 1);
                float c1y = __shfl_up_sync(0xffffffffu, cy, 1);
                float c0x = __shfl_up_sync(0xffffffffu, cx, 2);
                float c0y = __shfl_up_sync(0xffffffffu, cy, 2);
                float sa_l = 0.f;
                if (lane >= 2 && lane < cnt) {
                    float ax = (cx - 2.f * c1x + c0x) * SCALE_C;
                    float ay = (cy - 2.f * c1y + c0y) * SCALE_C;
                    sa_l = sqrtf(ax * ax + ay * ay);
                }
                #pragma unroll
                for (int o = 16; o > 0; o >>= 1)
                    sa_l += __shfl_down_sync(0xffffffffu, sa_l, o);
                if (lane == 0) tsum += sa_l / (float)(cnt - 2);
            } else if (lane == 0) {
                // serial fallback (data scale never hits this)
                int last = -1;
                float c0x = 0.f, c0y = 0.f, c1x = 0.f, c1y = 0.f;
                float sa = 0.f;
                for (int q = 0; q < cnt; q++) {
                    int m = 0x7fffffff;
                    for (int a = 0; a < cnt; a++) {
                        int vv = g_tpl[b][off + a];
                        if (vv > last && vv < m) m = vv;
                    }
                    last = m;
                    float4 bxx = pb4[m];
                    float cx = (bxx.x + bxx.z) * 0.5f;
                    float cy = (bxx.y + bxx.w) * 0.5f;
                    if (q >= 2) {
                        float ax = (cx - 2.f * c1x + c0x) * SCALE_C;
                        float ay = (cy - 2.f * c1y + c0y) * SCALE_C;
                        sa += sqrtf(ax * ax + ay * ay);
                    }
                    c0x = c1x; c0y = c1y; c1x = cx; c1y = cy;
                }
                tsum += sa / (float)(cnt - 2);
            }
        }
        if (lane == 0 && tsum != 0.f)
            atomicAdd(&g_traw[b], tsum);
    }

    // ---- last-block-done finalize ----
    __syncthreads();
    if (tid == 0) {
        __threadfence();
        int prev = atomicAdd(&g_done, 1);
        s_last = (prev == K3_TOTAL - 1) ? 1 : 0;
    }
    __syncthreads();
    if (s_last && tid < 32) {
        __threadfence();
        float lt = 0.f, ls = 0.f, lm = 0.f, nt = 0.f;
        if (tid < BB) {
            int bb = tid;
            int nv = g_nvalid[bb];
            int nu = g_nuni[bb];
            float has = (nv > 0) ? 1.f : 0.f;
            float mt  = *((volatile float*)&g_match[bb]);
            float fpb = *((volatile float*)&g_fp[bb]);
            int   sw  = *((volatile int*)&g_sw[bb]);
            float trw = *((volatile float*)&g_traw[bb]);
            float tr = B_FN * g_fn[bb] + mt + G_SW * (float)sw + B_FP * fpb;
            float tmp = (nv > 2) ? trw / fmaxf((float)nu, 1.f) : 0.f;
            lt = tr * has;
            ls = g_spatial[bb] * has;
            lm = tmp * has;
            nt = (float)nu * has;
        }
        #pragma unroll
        for (int o = 16; o > 0; o >>= 1) {
            lt += __shfl_down_sync(0xffffffffu, lt, o);
            ls += __shfl_down_sync(0xffffffffu, ls, o);
            lm += __shfl_down_sync(0xffffffffu, lm, o);
            nt += __shfl_down_sync(0xffffffffu, nt, o);
        }
        if (tid == 0) {
            float norm = (nt > 0.f) ? nt : 1.f;
            lt /= norm; ls /= norm; lm /= norm;
            out[0] = A_TRK * lt + A_SPA * ls + A_TMP * lm;
            out[1] = lt;
            out[2] = ls;
            out[3] = lm;
        }
    }
}

// ======================= launch =======================
extern "C" void kernel_launch(void* const* d_in, const int* in_sizes, int n_in,
                              void* d_out, int out_size)
{
    const float4* pb  = (const float4*)d_in[0];  // pred_boxes [16,2048,4] f32
    const float4* gb  = (const float4*)d_in[1];  // gt_boxes   [16,1024,4] f32
    const int*    pid = (const int*)d_in[2];     // pred_track_ids [16,2048] i32
    const int*    gid = (const int*)d_in[3];     // gt_track_ids   [16,1024] i32
    float* out = (float*)d_out;

    k1_prep<<<dim3(2, BB), 1024>>>(pb, gb, pid, gid);
    k3_main<<<dim3(K3_BX, BB), 256>>>(pb, out);
}

// round 17
// speedup vs baseline: 1.6839x; 1.0769x over previous
#include <cuda_runtime.h>
#include <cstdint>

#define BB 16
#define NN 2048
#define MM 1024
#define TT 256

#define SCALE_C (4.5392368437151541e-04f)  // 1/sqrt(1920^2+1080^2)
#define A_TRK 2.0f
#define A_SPA 1.5f
#define A_TMP 1.8f
#define B_FP 0.9f
#define B_FN 0.9f
#define G_SW 1.5f

#define NCX 16
#define NCELL 256
#define CELL_SCALE 0.016f       // 1/62.5
#define CMAX 15
#define F_INF __int_as_float(0x7f800000)

#define K3_SWEEP 32              // sweep blocks per batch (64 preds each)
#define K3_TEMP  5               // temporal blocks per batch
#define K3_BX (K3_SWEEP + K3_TEMP)          // 37
#define K3_TOTAL (K3_BX * BB)               // 592 = 4 * 148

// ---------------- device scratch (no allocations allowed) ----------------
__device__ int    g_gt_cnt[BB][TT];
__device__ int    g_pr_cnt[BB][TT];
__device__ int    g_csr_off[BB][TT];    // exclusive prefix of gt_cnt (track CSR)
__device__ int    g_csr[BB][MM];        // SORTED gt positions grouped by track id
__device__ float4 g_sgb[BB][MM];        // cell-sorted gt boxes
__device__ float  g_sa2[BB][MM];        // cell-sorted a2 (or +INF if track has no preds)
__device__ int    g_goff[BB][NCELL + 1];// gt cell CSR offsets
__device__ float4 g_spb[BB][NN];        // cell-sorted pred boxes
__device__ int    g_spid[BB][NN];       // cell-sorted pred ids
__device__ int    g_proff[BB][TT];      // pred-track CSR offsets
__device__ int    g_tpl[BB][NN];        // pred indices grouped by track (unordered)
__device__ float  g_fn[BB];
__device__ int    g_nuni[BB];
__device__ int    g_nvalid[BB];
__device__ float  g_match[BB];
__device__ float  g_fp[BB];
__device__ int    g_sw[BB];
__device__ float  g_spatial[BB];
__device__ float  g_traw[BB];
__device__ int    g_done;

// ======================= K1: grid (2, BB). role 0 = pred side, role 1 = gt side ==============
__global__ __launch_bounds__(1024) void k1_prep(
    const float4* __restrict__ pboxes,
    const float4* __restrict__ gboxes,
    const int*    __restrict__ pid,
    const int*    __restrict__ gid)
{
    const int role = blockIdx.x;
    const int b = blockIdx.y;
    const int tid = threadIdx.x;
    const int lane = tid & 31, w = tid >> 5;

    const int* pidb = pid + b * NN;

    if (role == 0) {
        // ================== PRED BLOCK ==================
        __shared__ int   s_pr[TT];
        __shared__ float s_mw[TT], s_mh[TT], s_dw[TT], s_dh[TT];
        __shared__ int   s_proff[TT], s_prcur[TT];
        __shared__ int   s_pcnt[NCELL], s_poffs[NCELL], s_pcur[NCELL];
        __shared__ int   s_p[NN];            // packed: pid | (cell<<8)
        __shared__ int   s_ws[2][8];
        __shared__ float r_s[32];
        __shared__ int   r_u[32], r_v[32];

        if (tid < TT) {
            s_pr[tid] = 0;
            s_mw[tid] = 0.f; s_mh[tid] = 0.f;
            s_dw[tid] = 0.f; s_dh[tid] = 0.f;
            s_pcnt[tid] = 0; s_pcur[tid] = 0;
        }
        if (b == 0 && tid == 0) g_done = 0;
        if (tid == 0) { g_match[b] = 0.f; g_fp[b] = 0.f; g_sw[b] = 0; g_traw[b] = 0.f; }
        __syncthreads();

        const float4* pb4 = pboxes + b * NN;
        int nvalid = 0;
        #pragma unroll
        for (int k = 0; k < 2; k++) {
            int i = tid + k * 1024;
            int p = pidb[i];
            float4 bx = pb4[i];
            int cx = min((int)(bx.x * CELL_SCALE), CMAX);
            int cy = min((int)(bx.y * CELL_SCALE), CMAX);
            int c = cy * NCX + cx;
            s_p[i] = p | (c << 8);
            atomicAdd(&s_pcnt[c], 1);
            if (p > 0) {
                atomicAdd(&s_pr[p], 1);
                atomicAdd(&s_mw[p], bx.z - bx.x);
                atomicAdd(&s_mh[p], bx.w - bx.y);
                nvalid++;
            }
        }
        __syncthreads();

        // means + publish counts
        if (tid < TT) {
            int c = s_pr[tid];
            float cs = fmaxf((float)c, 1.f);
            s_mw[tid] = s_mw[tid] / cs;
            s_mh[tid] = s_mh[tid] / cs;
            g_pr_cnt[b][tid] = c;
        }
        // two parallel 256-bin scans: seg 0 = pred cells, seg 1 = pred-track
        {
            const int seg = tid >> 8;            // 0..3
            const int c = tid & 255;
            const int w8 = (tid >> 5) & 7;
            int val = 0;
            if (seg == 0) val = s_pcnt[c];
            else if (seg == 1) val = s_pr[c];
            int incl = val;
            #pragma unroll
            for (int o = 1; o < 32; o <<= 1) {
                int n = __shfl_up_sync(0xffffffffu, incl, o);
                if (lane >= o) incl += n;
            }
            if (seg < 2 && lane == 31) s_ws[seg][w8] = incl;
            __syncthreads();
            if (seg < 2) {
                int woff = 0;
                #pragma unroll
                for (int k = 0; k < 8; k++) if (k < w8) woff += s_ws[seg][k];
                int excl = woff + incl - val;
                if (seg == 0) { s_poffs[c] = excl; }
                else          { s_proff[c] = excl; s_prcur[c] = 0; g_proff[b][c] = excl; }
            }
        }
        __syncthreads();

        // deviations + scatters
        #pragma unroll
        for (int k = 0; k < 2; k++) {
            int i = tid + k * 1024;
            int pk = s_p[i];
            int p = pk & 0xFF;
            int c = pk >> 8;
            float4 bx = pb4[i];                // L1-resident reload
            if (p > 0) {
                atomicAdd(&s_dw[p], fabsf((bx.z - bx.x) - s_mw[p]));
                atomicAdd(&s_dh[p], fabsf((bx.w - bx.y) - s_mh[p]));
                int tp = s_proff[p] + atomicAdd(&s_prcur[p], 1);
                g_tpl[b][tp] = i;
            }
            int pos = s_poffs[c] + atomicAdd(&s_pcur[c], 1);
            g_spb[b][pos] = bx;
            g_spid[b][pos] = p;
        }
        __syncthreads();

        // spatial / nuni / nvalid reduce
        float sp = 0.f;
        int nu = 0;
        if (tid < TT) {
            int c = s_pr[tid];
            nu = (c > 0) ? 1 : 0;
            sp = (c > 1) ? (s_dw[tid] + s_dh[tid]) * SCALE_C / (float)c : 0.f;
        }
        #pragma unroll
        for (int o = 16; o > 0; o >>= 1) {
            sp     += __shfl_down_sync(0xffffffffu, sp, o);
            nu     += __shfl_down_sync(0xffffffffu, nu, o);
            nvalid += __shfl_down_sync(0xffffffffu, nvalid, o);
        }
        if (lane == 0) { r_s[w] = sp; r_u[w] = nu; r_v[w] = nvalid; }
        __syncthreads();
        if (tid == 0) {
            float S = 0.f; int U = 0, V = 0;
            #pragma unroll
            for (int k = 0; k < 32; k++) { S += r_s[k]; U += r_u[k]; V += r_v[k]; }
            g_nuni[b] = U; g_nvalid[b] = V;
            g_spatial[b] = (V > 1) ? S / fmaxf((float)U, 1.f) : 0.f;
        }
    } else {
        // ================== GT BLOCK ==================
        __shared__ int   s_gt[TT], s_pr[TT];
        __shared__ int   s_toff[TT], s_tcur[TT];
        __shared__ int   s_gcnt[NCELL], s_goffs[NCELL], s_gcur[NCELL];
        __shared__ float s_ga2[MM];
        __shared__ int   s_ws[2][8];
        __shared__ float r_f[32];

        if (tid < TT) {
            s_gt[tid] = 0; s_pr[tid] = 0;
            s_gcnt[tid] = 0; s_gcur[tid] = 0;
        }
        __syncthreads();

        const int* gidb = gid + b * MM;
        const float4* gb4 = gboxes + b * MM;
        if (tid < MM) {
            float4 g = gb4[tid];
            int t = gidb[tid];
            float a2 = fmaxf(g.z - g.x, 0.f) * fmaxf(g.w - g.y, 0.f);
            int cx = min((int)(g.x * CELL_SCALE), CMAX);
            int cy = min((int)(g.y * CELL_SCALE), CMAX);
            s_ga2[tid] = a2;
            atomicAdd(&s_gt[t], 1);
            atomicAdd(&s_gcnt[cy * NCX + cx], 1);
        }
        // rebuild pred-track counts (needed for a2/INF flag and fn)
        #pragma unroll
        for (int k = 0; k < 2; k++) {
            int p = pidb[tid + k * 1024];
            if (p > 0) atomicAdd(&s_pr[p], 1);
        }
        __syncthreads();

        if (tid < TT) g_gt_cnt[b][tid] = s_gt[tid];
        // two parallel scans: seg 0 = gt track (CSR), seg 1 = gt cells
        {
            const int seg = tid >> 8;
            const int c = tid & 255;
            const int w8 = (tid >> 5) & 7;
            int val = 0;
            if (seg == 0) val = s_gt[c];
            else if (seg == 1) val = s_gcnt[c];
            int incl = val;
            #pragma unroll
            for (int o = 1; o < 32; o <<= 1) {
                int n = __shfl_up_sync(0xffffffffu, incl, o);
                if (lane >= o) incl += n;
            }
            if (seg < 2 && lane == 31) s_ws[seg][w8] = incl;
            __syncthreads();
            if (seg < 2) {
                int woff = 0;
                #pragma unroll
                for (int k = 0; k < 8; k++) if (k < w8) woff += s_ws[seg][k];
                int excl = woff + incl - val;
                if (seg == 0) { s_toff[c] = excl; s_tcur[c] = 0; g_csr_off[b][c] = excl; }
                else          { s_goffs[c] = excl; g_goff[b][c] = excl;
                                if (c == 0) g_goff[b][NCELL] = MM; }
            }
        }
        __syncthreads();

        // gt scatter + CSR
        if (tid < MM) {
            int j = tid;
            float4 g = gb4[j];                 // L1-resident reload
            int t = gidb[j];
            int cx = min((int)(g.x * CELL_SCALE), CMAX);
            int cy = min((int)(g.y * CELL_SCALE), CMAX);
            int c = cy * NCX + cx;
            int pos = s_goffs[c] + atomicAdd(&s_gcur[c], 1);
            g_sgb[b][pos] = g;
            g_sa2[b][pos] = (s_pr[t] > 0) ? s_ga2[j] : F_INF;
            int tp = s_toff[t] + atomicAdd(&s_tcur[t], 1);
            g_csr[b][tp] = pos;
        }
        __syncthreads();

        // fn reduce
        float fn = 0.f;
        if (tid < TT) {
            int gc = s_gt[tid];
            fn = (gc > 0 && s_pr[tid] == 0) ? (float)gc : 0.f;
        }
        #pragma unroll
        for (int o = 16; o > 0; o >>= 1)
            fn += __shfl_down_sync(0xffffffffu, fn, o);
        if (lane == 0) r_f[w] = fn;
        __syncthreads();
        if (tid == 0) {
            float F = 0.f;
            #pragma unroll
            for (int k = 0; k < 32; k++) F += r_f[k];
            g_fn[b] = F;
        }
    }
}

// ======================= K3: sweep blocks + temporal blocks + finalize =======================
// grid (37, BB), 256 threads. bx<32: 64 preds/block, PER-PRED window, msplit over cell rows.
// bx>=32: temporal, 8 warps x 7 tracks each (40 warps cover 256 tracks).
__global__ __launch_bounds__(256) void k3_main(
    const float4* __restrict__ pboxes,
    float* __restrict__ out)
{
    const int b = blockIdx.y;
    const int bx = blockIdx.x;
    const int tid = threadIdx.x;
    const int lane = tid & 31;
    const int wid = tid >> 5;

    __shared__ __align__(16) float4 s_gb[MM];   // sorted gt boxes  16 KB
    __shared__ __align__(16) float  s_a2[MM];   // sorted a2/INF     4 KB
    __shared__ int   s_goff[NCELL + 1];         // 1 KB
    __shared__ float sm_m, sm_f;
    __shared__ int   sm_s;
    __shared__ int   s_tsort[8][33];
    __shared__ int   s_last;

    if (bx < K3_SWEEP) {
        // ================= SWEEP BLOCK =================
        const float4* __restrict__ sgbg = g_sgb[b];
        const float*  __restrict__ sa2g = g_sa2[b];
        #pragma unroll
        for (int k = 0; k < 4; k++) {
            int j = tid + k * 256;
            s_gb[j] = sgbg[j];
            s_a2[j] = sa2g[j];
        }
        s_goff[tid] = g_goff[b][tid];
        if (tid == 0) {
            s_goff[NCELL] = g_goff[b][NCELL];
            sm_m = 0.f; sm_f = 0.f; sm_s = 0;
        }
        __syncthreads();

        const int pred_l = tid & 63;
        const int msplit = tid >> 6;                 // row-strided split of OWN window
        const int slot = bx * 64 + pred_l;
        const int p = g_spid[b][slot];               // coalesced
        const float4 pbx = g_spb[b][slot];           // coalesced
        const float px1 = pbx.x, py1 = pbx.y, px2 = pbx.z, py2 = pbx.w;
        const float a1r = fmaxf(px2 - px1, 0.f) * fmaxf(py2 - py1, 0.f);
        const float a1 = (p > 0) ? a1r : F_INF;      // INF => hi-test always false

        // PER-PRED window cells (conservative: gt corner in [px1-102, px2] x [py1-102, py2])
        const int cx0 = (int)(fmaxf(px1 - 103.f, 0.f) * CELL_SCALE);
        const int cx1 = min((int)((px2 + 1.f) * CELL_SCALE), CMAX);
        const int cy0 = (int)(fmaxf(py1 - 103.f, 0.f) * CELL_SCALE);
        const int cy1 = min((int)((py2 + 1.f) * CELL_SCALE), CMAX);

        int swc = 0;
        for (int cy = cy0 + msplit; cy <= cy1; cy += 4) {
            const int rowb = cy * NCX;
            const int jlo = s_goff[rowb + cx0];
            const int jhi = s_goff[rowb + cx1 + 1];
            #pragma unroll 4
            for (int j = jlo; j < jhi; j++) {
                float4 g = s_gb[j];
                float a2 = s_a2[j];
                float lx = fmaxf(px1, g.x), ly = fmaxf(py1, g.y);
                float rx = fminf(px2, g.z), ry = fminf(py2, g.w);
                float inter = (rx - lx) * fmaxf(ry - ly, 0.f);   // single-clamp
                swc += (fmaf(3.f, inter, -a1) > a2);
            }
        }

        float matchv = 0.f, fpv = 0.f;
        if (msplit == 0 && p > 0) {
            int gc = g_gt_cnt[b][p];
            if (gc > 0) {
                int off = g_csr_off[b][p];
                float bn = 0.f, bd = 1.f;
                for (int k = 0; k < gc; k++) {
                    int pos = g_csr[b][off + k];
                    float4 g = s_gb[pos];
                    float a2 = s_a2[pos];            // own track => finite
                    float lx = fmaxf(px1, g.x), ly = fmaxf(py1, g.y);
                    float rx = fminf(px2, g.z), ry = fminf(py2, g.w);
                    float iw = rx - lx;
                    float ihc = fmaxf(ry - ly, 0.f);
                    float interh = iw * ihc;                       // identical hi-test
                    swc -= (fmaf(3.f, interh, -a1) > a2);
                    float inter = fmaxf(iw, 0.f) * ihc;            // true inter for IoU
                    float uni = a1r + a2 - inter;
                    if (inter * bd > bn * uni) { bn = inter; bd = uni; }
                }
                matchv = 1.f - __fdividef(bn, bd);
            } else {
                fpv = 1.f;
            }
        }

        // warp reduce -> smem combine -> 3 atomics per block
        #pragma unroll
        for (int o = 16; o > 0; o >>= 1) {
            matchv += __shfl_down_sync(0xffffffffu, matchv, o);
            fpv    += __shfl_down_sync(0xffffffffu, fpv, o);
            swc    += __shfl_down_sync(0xffffffffu, swc, o);
        }
        if (lane == 0) {
            atomicAdd(&sm_m, matchv);
            atomicAdd(&sm_f, fpv);
            atomicAdd(&sm_s, swc);
        }
        __syncthreads();
        if (tid == 0) {
            atomicAdd(&g_match[b], sm_m);
            atomicAdd(&g_fp[b], sm_f);
            atomicAdd(&g_sw[b], sm_s);
        }
    } else {
        // ================= TEMPORAL BLOCK =================
        const float4* pb4 = pboxes + b * NN;
        const int tw = (bx - K3_SWEEP) * 8 + wid;    // 0..39
        float tsum = 0.f;
        #pragma unroll
        for (int k = 0; k < 7; k++) {
            const int t = tw * 7 + k;                // 0..279, warp-uniform
            if (t == 0 || t >= TT) continue;
            const int cnt = g_pr_cnt[b][t];
            if (cnt <= 2) continue;
            const int off = g_proff[b][t];
            if (cnt <= 32) {
                int v = (lane < cnt) ? g_tpl[b][off + lane] : 0x7fffffff;
                int rank = 0;
                for (int o = 1; o < cnt; o++) {
                    int src = lane + o;
                    if (src >= cnt) src -= cnt;
                    int ov = __shfl_sync(0xffffffffu, v, src);
                    rank += (ov < v);
                }
                if (lane < cnt) s_tsort[wid][rank] = v;
                __syncwarp();
                int myidx = (lane < cnt) ? s_tsort[wid][lane] : 0;
                float cx = 0.f, cy = 0.f;
                if (lane < cnt) {
                    float4 bxx = pb4[myidx];
                    cx = (bxx.x + bxx.z) * 0.5f;
                    cy = (bxx.y + bxx.w) * 0.5f;
                }
                float c1x = __shfl_up_sync(0xffffffffu, cx, 1);
                float c1y = __shfl_up_sync(0xffffffffu, cy, 1);
                float c0x = __shfl_up_sync(0xffffffffu, cx, 2);
                float c0y = __shfl_up_sync(0xffffffffu, cy, 2);
                float sa_l = 0.f;
                if (lane >= 2 && lane < cnt) {
                    float ax = (cx - 2.f * c1x + c0x) * SCALE_C;
                    float ay = (cy - 2.f * c1y + c0y) * SCALE_C;
                    sa_l = sqrtf(ax * ax + ay * ay);
                }
                #pragma unroll
                for (int o = 16; o > 0; o >>= 1)
                    sa_l += __shfl_down_sync(0xffffffffu, sa_l, o);
                if (lane == 0) tsum += sa_l / (float)(cnt - 2);
            } else if (lane == 0) {
                // serial fallback (data scale never hits this)
                int last = -1;
                float c0x = 0.f, c0y = 0.f, c1x = 0.f, c1y = 0.f;
                float sa = 0.f;
                for (int q = 0; q < cnt; q++) {
                    int m = 0x7fffffff;
                    for (int a = 0; a < cnt; a++) {
                        int vv = g_tpl[b][off + a];
                        if (vv > last && vv < m) m = vv;
                    }
                    last = m;
                    float4 bxx = pb4[m];
                    float cx = (bxx.x + bxx.z) * 0.5f;
                    float cy = (bxx.y + bxx.w) * 0.5f;
                    if (q >= 2) {
                        float ax = (cx - 2.f * c1x + c0x) * SCALE_C;
                        float ay = (cy - 2.f * c1y + c0y) * SCALE_C;
                        sa += sqrtf(ax * ax + ay * ay);
                    }
                    c0x = c1x; c0y = c1y; c1x = cx; c1y = cy;
                }
                tsum += sa / (float)(cnt - 2);
            }
        }
        if (lane == 0 && tsum != 0.f)
            atomicAdd(&g_traw[b], tsum);
    }

    // ---- last-block-done finalize ----
    __syncthreads();
    if (tid == 0) {
        __threadfence();
        int prev = atomicAdd(&g_done, 1);
        s_last = (prev == K3_TOTAL - 1) ? 1 : 0;
    }
    __syncthreads();
    if (s_last && tid < 32) {
        __threadfence();
        float lt = 0.f, ls = 0.f, lm = 0.f, nt = 0.f;
        if (tid < BB) {
            int bb = tid;
            int nv = g_nvalid[bb];
            int nu = g_nuni[bb];
            float has = (nv > 0) ? 1.f : 0.f;
            float mt  = *((volatile float*)&g_match[bb]);
            float fpb = *((volatile float*)&g_fp[bb]);
            int   sw  = *((volatile int*)&g_sw[bb]);
            float trw = *((volatile float*)&g_traw[bb]);
            float tr = B_FN * g_fn[bb] + mt + G_SW * (float)sw + B_FP * fpb;
            float tmp = (nv > 2) ? trw / fmaxf((float)nu, 1.f) : 0.f;
            lt = tr * has;
            ls = g_spatial[bb] * has;
            lm = tmp * has;
            nt = (float)nu * has;
        }
        #pragma unroll
        for (int o = 16; o > 0; o >>= 1) {
            lt += __shfl_down_sync(0xffffffffu, lt, o);
            ls += __shfl_down_sync(0xffffffffu, ls, o);
            lm += __shfl_down_sync(0xffffffffu, lm, o);
            nt += __shfl_down_sync(0xffffffffu, nt, o);
        }
        if (tid == 0) {
            float norm = (nt > 0.f) ? nt : 1.f;
            lt /= norm; ls /= norm; lm /= norm;
            out[0] = A_TRK * lt + A_SPA * ls + A_TMP * lm;
            out[1] = lt;
            out[2] = ls;
            out[3] = lm;
        }
    }
}

// ======================= launch =======================
extern "C" void kernel_launch(void* const* d_in, const int* in_sizes, int n_in,
                              void* d_out, int out_size)
{
    const float4* pb  = (const float4*)d_in[0];  // pred_boxes [16,2048,4] f32
    const float4* gb  = (const float4*)d_in[1];  // gt_boxes   [16,1024,4] f32
    const int*    pid = (const int*)d_in[2];     // pred_track_ids [16,2048] i32
    const int*    gid = (const int*)d_in[3];     // gt_track_ids   [16,1024] i32
    float* out = (float*)d_out;

    k1_prep<<<dim3(2, BB), 1024>>>(pb, gb, pid, gid);
    k3_main<<<dim3(K3_BX, BB), 256>>>(pb, out);
}